// round 2
// baseline (speedup 1.0000x reference)
#include <cuda_runtime.h>

// Problem constants
#define NB 32768   // number of signals (B)
#define NA 512     // number of atoms (N)
#define MD 64      // embedding dim (M)
#define SP 5       // sparsity
#define ZELEMS 2097152        // 32*64*32*32
#define LOSS_OFF ZELEMS       // loss scalar offset in d_out
#define COEF_OFF (ZELEMS + 1) // coefficients offset in d_out

// Scratch (static __device__ — no allocation allowed)
__device__ float g_Zt[NB * MD];   // Z transposed: [j][m], 8 MB
__device__ float g_H[NB * NA];    // h_bar: [j][n], 64 MB
__device__ float g_G[NA * NA];    // Gram D^T D, 1 MB
__device__ float g_Dt[NA * MD];   // D transposed: [n][m], 128 KB

// ---------------------------------------------------------------------------
// Zero the loss slot + coefficient region of d_out
// ---------------------------------------------------------------------------
__global__ void k_zero(float* __restrict__ out, int nfloats) {
    float4* p = (float4*)(out + LOSS_OFF);
    int n4 = nfloats >> 2;
    for (int i = blockIdx.x * blockDim.x + threadIdx.x; i < n4;
         i += gridDim.x * blockDim.x)
        p[i] = make_float4(0.f, 0.f, 0.f, 0.f);
    if (blockIdx.x == 0 && threadIdx.x < (nfloats & 3))
        out[LOSS_OFF + (n4 << 2) + threadIdx.x] = 0.f;
}

// ---------------------------------------------------------------------------
// Scatter z_e (NCHW) -> Zt[j][m] replicating the reference's permute+reshape
// g = ((b*64 + c)*32 + h)*32 + w ;  f = ((b*32+h)*32+w)*64 + c
// r = f>>15 ; j = f & 32767 ; Zt[j*64 + r] = z_e[g]
// ---------------------------------------------------------------------------
__global__ void k_scatter(const float* __restrict__ ze) {
    int g = blockIdx.x * blockDim.x + threadIdx.x;
    if (g >= ZELEMS) return;
    float v = ze[g];
    int b = g >> 16;
    int c = (g >> 10) & 63;
    int h = (g >> 5) & 31;
    int w = g & 31;
    int f = ((((b << 5) | h) << 5) | w) << 6 | c;
    g_Zt[(f & (NB - 1)) * MD + (f >> 15)] = v;
}

// ---------------------------------------------------------------------------
// Transpose dictionary: Dt[n][m] = D[m][n]
// ---------------------------------------------------------------------------
__global__ void k_dtrans(const float* __restrict__ D) {
    int t = blockIdx.x * blockDim.x + threadIdx.x;
    if (t >= MD * NA) return;
    int m = t >> 9;
    int n = t & (NA - 1);
    g_Dt[n * MD + m] = D[t];
}

// ---------------------------------------------------------------------------
// Gram matrix G[a][b] = sum_m D[m][a]*D[m][b]. 32x32 tile per block.
// ---------------------------------------------------------------------------
__global__ void k_gram(const float* __restrict__ D) {
    __shared__ float Da[32 * 65];
    __shared__ float Db[32 * 65];
    int a0 = blockIdx.y * 32, b0 = blockIdx.x * 32;
    int t = threadIdx.x;  // 256
#pragma unroll
    for (int it = 0; it < 8; it++) {
        int e = t + it * 256;  // 2048
        int aa = e & 31, m = e >> 5;
        Da[aa * 65 + m] = D[m * NA + a0 + aa];
        Db[aa * 65 + m] = D[m * NA + b0 + aa];
    }
    __syncthreads();
    int tb = t & 15, ta = t >> 4;
    float acc[2][2] = {};
#pragma unroll
    for (int m = 0; m < MD; m++) {
        float a0v = Da[(2 * ta) * 65 + m];
        float a1v = Da[(2 * ta + 1) * 65 + m];
        float b0v = Db[(2 * tb) * 65 + m];
        float b1v = Db[(2 * tb + 1) * 65 + m];
        acc[0][0] += a0v * b0v; acc[0][1] += a0v * b1v;
        acc[1][0] += a1v * b0v; acc[1][1] += a1v * b1v;
    }
#pragma unroll
    for (int i = 0; i < 2; i++)
#pragma unroll
        for (int l = 0; l < 2; l++)
            g_G[(a0 + 2 * ta + i) * NA + (b0 + 2 * tb + l)] = acc[i][l];
}

// ---------------------------------------------------------------------------
// GEMM: H[j][n] = sum_m Zt[j][m] * D[m][n]   (512 x 32768 x 64, fp32)
// Tile: 128 j x 64 n per block, full K=64 in smem. 256 threads, 8x4 per thread.
// ---------------------------------------------------------------------------
__global__ __launch_bounds__(256) void k_gemm(const float* __restrict__ D) {
    __shared__ float Zs[128 * 65];
    __shared__ __align__(16) float Ds[64 * 64];
    int j0 = blockIdx.x * 128;
    int n0 = blockIdx.y * 64;
    int t = threadIdx.x;
#pragma unroll
    for (int it = 0; it < 32; it++) {
        int e = t + it * 256;  // 8192
        int jj = e >> 6, m = e & 63;
        Zs[jj * 65 + m] = g_Zt[(j0 + jj) * MD + m];
    }
#pragma unroll
    for (int it = 0; it < 16; it++) {
        int e = t + it * 256;  // 4096
        int m = e >> 6, nn = e & 63;
        Ds[e] = D[m * NA + n0 + nn];
    }
    __syncthreads();
    int tx = t & 15, ty = t >> 4;
    float acc[8][4] = {};
#pragma unroll
    for (int m = 0; m < 64; m++) {
        float4 dv = *(const float4*)&Ds[m * 64 + tx * 4];
#pragma unroll
        for (int i = 0; i < 8; i++) {
            float z = Zs[(ty * 8 + i) * 65 + m];
            acc[i][0] += z * dv.x;
            acc[i][1] += z * dv.y;
            acc[i][2] += z * dv.z;
            acc[i][3] += z * dv.w;
        }
    }
#pragma unroll
    for (int i = 0; i < 8; i++) {
        int j = j0 + ty * 8 + i;
        *(float4*)&g_H[(size_t)j * NA + n0 + tx * 4] =
            make_float4(acc[i][0], acc[i][1], acc[i][2], acc[i][3]);
    }
}

// ---------------------------------------------------------------------------
// OMP: one warp per signal. 4 warps/block, launch_bounds caps regs for 3
// blocks/SM (12 warps/SM). Selected G rows cached in registers.
// ---------------------------------------------------------------------------
__global__ __launch_bounds__(128, 3) void k_omp(float* __restrict__ out) {
    int warp = threadIdx.x >> 5;
    int lane = threadIdx.x & 31;
    int j = blockIdx.x * 4 + warp;

    // load h_bar for this signal: lane holds n = lane + 32*q
    float hbar[16];
    const float* hrow = g_H + (size_t)j * NA;
#pragma unroll
    for (int q = 0; q < 16; q++) hbar[q] = hrow[lane + (q << 5)];

    float Grow[SP][16];  // cached G rows of selected atoms
    float L[SP][SP];
    float x[SP];
    float hb[SP];
    int I[SP];
    unsigned mask16 = 0;

#pragma unroll
    for (int k = 1; k <= SP; k++) {
        // masked argmax of |h_bar - sum_{i<k-1} x_i * G[I_i]| (first-max on tie)
        float bestu = -1.0f;
        int bestn = 0;
        float bhb = 0.0f;
#pragma unroll
        for (int q = 0; q < 16; q++) {
            float h = hbar[q];
#pragma unroll
            for (int i = 0; i < k - 1; i++) h -= x[i] * Grow[i][q];
            float u = ((mask16 >> q) & 1u) ? 0.0f : fabsf(h);
            if (u > bestu) { bestu = u; bestn = lane + (q << 5); bhb = hbar[q]; }
        }
#pragma unroll
        for (int off = 16; off; off >>= 1) {
            float ou = __shfl_xor_sync(0xFFFFFFFFu, bestu, off);
            int on = __shfl_xor_sync(0xFFFFFFFFu, bestn, off);
            float ob = __shfl_xor_sync(0xFFFFFFFFu, bhb, off);
            if (ou > bestu || (ou == bestu && on < bestn)) {
                bestu = ou; bestn = on; bhb = ob;
            }
        }
        I[k - 1] = bestn;
        hb[k - 1] = bhb;
        if ((bestn & 31) == lane) mask16 |= 1u << (bestn >> 5);

        // cache the new atom's G row
        const float* grow = g_G + bestn * NA;
#pragma unroll
        for (int q = 0; q < 16; q++) Grow[k - 1][q] = grow[lane + (q << 5)];

        // Cholesky-style L update (all lanes redundantly)
        if (k == 1) {
            L[0][0] = 1.0f;
        } else {
            float gv[SP - 1];
#pragma unroll
            for (int i = 0; i < k - 1; i++) gv[i] = g_G[I[i] * NA + bestn];
            float w[SP - 1];
            float ss = 0.0f;
#pragma unroll
            for (int i = 0; i < k - 1; i++) {
                float s = gv[i];
#pragma unroll
                for (int j2 = 0; j2 < i; j2++) s -= L[i][j2] * w[j2];
                w[i] = s / L[i][i];
                ss += w[i] * w[i];
            }
#pragma unroll
            for (int j2 = 0; j2 < k - 1; j2++) L[k - 1][j2] = w[j2];
            L[k - 1][k - 1] = sqrtf(fmaxf(1.0f - ss, 0.0f));
        }

        // y = L^{-1} hb ; x = L^{-T} y
        float y[SP];
#pragma unroll
        for (int i = 0; i < k; i++) {
            float s = hb[i];
#pragma unroll
            for (int j2 = 0; j2 < i; j2++) s -= L[i][j2] * y[j2];
            y[i] = s / L[i][i];
        }
#pragma unroll
        for (int i = k - 1; i >= 0; i--) {
            float s = y[i];
#pragma unroll
            for (int j2 = i + 1; j2 < k; j2++) s -= L[j2][i] * x[j2];
            x[i] = s / L[i][i];
        }
    }

    // reconstruction: recon[m] = sum_i x_i * D[m][I_i]
    float ze0 = g_Zt[j * MD + lane];
    float ze1 = g_Zt[j * MD + 32 + lane];
    float r0 = 0.f, r1 = 0.f;
#pragma unroll
    for (int i = 0; i < SP; i++) {
        const float* dcol = g_Dt + I[i] * MD;
        r0 += x[i] * dcol[lane];
        r1 += x[i] * dcol[32 + lane];
    }

    // z_out = ze + (recon - ze), scattered back to NCHW
    // f = m*32768 + j = ((b*32+h)*32+w)*64 + c
    // -> c = f&63, w = (f>>6)&31, h = (f>>11)&31, b = f>>16
#pragma unroll
    for (int p = 0; p < 2; p++) {
        int m = lane + 32 * p;
        float rm = p ? r1 : r0;
        float ze = p ? ze1 : ze0;
        float zo = ze + (rm - ze);
        int f = (m << 15) | j;
        int c = f & 63, ww = (f >> 6) & 31, hh = (f >> 11) & 31, bb = f >> 16;
        out[((bb * 64 + c) * 32 + hh) * 32 + ww] = zo;
    }

    // loss partial: 1.25 * mean((recon - ze)^2)
    float d0 = r0 - ze0, d1 = r1 - ze1;
    float s = d0 * d0 + d1 * d1;
#pragma unroll
    for (int off = 16; off; off >>= 1) s += __shfl_xor_sync(0xFFFFFFFFu, s, off);
    __shared__ float bsum[4];
    if (lane == 0) bsum[warp] = s;
    __syncthreads();
    if (threadIdx.x == 0) {
        float t = bsum[0] + bsum[1] + bsum[2] + bsum[3];
        atomicAdd(out + LOSS_OFF, t * (1.25f / (float)ZELEMS));
    }

    // scatter the 5 coefficients
    if (lane == 0) {
        float* co = out + COEF_OFF;
        co[(size_t)I[0] * NB + j] = x[0];
        co[(size_t)I[1] * NB + j] = x[1];
        co[(size_t)I[2] * NB + j] = x[2];
        co[(size_t)I[3] * NB + j] = x[3];
        co[(size_t)I[4] * NB + j] = x[4];
    }
}

// ---------------------------------------------------------------------------
extern "C" void kernel_launch(void* const* d_in, const int* in_sizes, int n_in,
                              void* d_out, int out_size) {
    const float* ze = (const float*)d_in[0];  // (32, 64, 32, 32)
    const float* D = (const float*)d_in[1];   // (64, 512)
    float* out = (float*)d_out;

    int ztail = out_size - LOSS_OFF;  // loss + coefficients
    k_zero<<<4096, 256>>>(out, ztail);
    k_scatter<<<(ZELEMS + 255) / 256, 256>>>(ze);
    k_dtrans<<<(MD * NA + 255) / 256, 256>>>(D);
    k_gram<<<dim3(16, 16), 256>>>(D);
    k_gemm<<<dim3(NB / 128, NA / 64), 256>>>(D);
    k_omp<<<NB / 4, 128>>>(out);
}

// round 3
// speedup vs baseline: 1.1004x; 1.1004x over previous
#include <cuda_runtime.h>

// Problem constants
#define NB 32768   // number of signals (B)
#define NA 512     // number of atoms (N)
#define MD 64      // embedding dim (M)
#define SP 5       // sparsity
#define ZELEMS 2097152        // 32*64*32*32
#define LOSS_OFF ZELEMS       // loss scalar offset in d_out
#define COEF_OFF (ZELEMS + 1) // coefficients offset in d_out

// Scratch (static __device__ — no allocation allowed)
__device__ float g_Zt[NB * MD];   // Z transposed: [j][m], 8 MB
__device__ float g_H[NB * NA];    // h_bar: [j][n], 64 MB
__device__ float g_G[NA * NA];    // Gram D^T D, 1 MB
__device__ float g_Dt[NA * MD];   // D transposed: [n][m], 128 KB

// ---------------------------------------------------------------------------
// Zero the loss slot + coefficient region of d_out, and transpose D -> Dt
// ---------------------------------------------------------------------------
__global__ void k_prep(float* __restrict__ out, int nfloats,
                       const float* __restrict__ D) {
    int tid = blockIdx.x * blockDim.x + threadIdx.x;
    float4* p = (float4*)(out + LOSS_OFF);
    int n4 = nfloats >> 2;
    for (int i = tid; i < n4; i += gridDim.x * blockDim.x)
        p[i] = make_float4(0.f, 0.f, 0.f, 0.f);
    if (blockIdx.x == 0 && threadIdx.x < (nfloats & 3))
        out[LOSS_OFF + (n4 << 2) + threadIdx.x] = 0.f;
    if (tid < MD * NA) {
        int m = tid >> 9;
        int n = tid & (NA - 1);
        g_Dt[n * MD + m] = D[tid];
    }
}

// ---------------------------------------------------------------------------
// Scatter z_e (NCHW) -> Zt[j][m] replicating the reference's permute+reshape
// g = ((b*64 + c)*32 + h)*32 + w ;  f = ((b*32+h)*32+w)*64 + c
// r = f>>15 ; j = f & 32767 ; Zt[j*64 + r] = z_e[g]
// ---------------------------------------------------------------------------
__global__ void k_scatter(const float* __restrict__ ze) {
    int g = blockIdx.x * blockDim.x + threadIdx.x;
    if (g >= ZELEMS) return;
    float v = ze[g];
    int b = g >> 16;
    int c = (g >> 10) & 63;
    int h = (g >> 5) & 31;
    int w = g & 31;
    int f = ((((b << 5) | h) << 5) | w) << 6 | c;
    g_Zt[(f & (NB - 1)) * MD + (f >> 15)] = v;
}

// ---------------------------------------------------------------------------
// Gram matrix G[a][b] = sum_m D[m][a]*D[m][b]. 32x32 tile per block.
// ---------------------------------------------------------------------------
__global__ void k_gram(const float* __restrict__ D) {
    __shared__ float Da[32 * 65];
    __shared__ float Db[32 * 65];
    int a0 = blockIdx.y * 32, b0 = blockIdx.x * 32;
    int t = threadIdx.x;  // 256
#pragma unroll
    for (int it = 0; it < 8; it++) {
        int e = t + it * 256;  // 2048
        int aa = e & 31, m = e >> 5;
        Da[aa * 65 + m] = D[m * NA + a0 + aa];
        Db[aa * 65 + m] = D[m * NA + b0 + aa];
    }
    __syncthreads();
    int tb = t & 15, ta = t >> 4;
    float acc[2][2] = {};
#pragma unroll
    for (int m = 0; m < MD; m++) {
        float a0v = Da[(2 * ta) * 65 + m];
        float a1v = Da[(2 * ta + 1) * 65 + m];
        float b0v = Db[(2 * tb) * 65 + m];
        float b1v = Db[(2 * tb + 1) * 65 + m];
        acc[0][0] += a0v * b0v; acc[0][1] += a0v * b1v;
        acc[1][0] += a1v * b0v; acc[1][1] += a1v * b1v;
    }
#pragma unroll
    for (int i = 0; i < 2; i++)
#pragma unroll
        for (int l = 0; l < 2; l++)
            g_G[(a0 + 2 * ta + i) * NA + (b0 + 2 * tb + l)] = acc[i][l];
}

// ---------------------------------------------------------------------------
// GEMM: H[j][n] = sum_m Zt[j][m] * D[m][n]   (512 x 32768 x 64, fp32)
// Tile: 128 j x 64 n per block, full K=64 in smem. 256 threads, 8x4 per thread.
// ---------------------------------------------------------------------------
__global__ __launch_bounds__(256) void k_gemm(const float* __restrict__ D) {
    __shared__ float Zs[128 * 65];
    __shared__ __align__(16) float Ds[64 * 64];
    int j0 = blockIdx.x * 128;
    int n0 = blockIdx.y * 64;
    int t = threadIdx.x;
#pragma unroll
    for (int it = 0; it < 32; it++) {
        int e = t + it * 256;  // 8192
        int jj = e >> 6, m = e & 63;
        Zs[jj * 65 + m] = g_Zt[(j0 + jj) * MD + m];
    }
#pragma unroll
    for (int it = 0; it < 16; it++) {
        int e = t + it * 256;  // 4096
        int m = e >> 6, nn = e & 63;
        Ds[e] = D[m * NA + n0 + nn];
    }
    __syncthreads();
    int tx = t & 15, ty = t >> 4;
    float acc[8][4] = {};
#pragma unroll
    for (int m = 0; m < 64; m++) {
        float4 dv = *(const float4*)&Ds[m * 64 + tx * 4];
#pragma unroll
        for (int i = 0; i < 8; i++) {
            float z = Zs[(ty * 8 + i) * 65 + m];
            acc[i][0] += z * dv.x;
            acc[i][1] += z * dv.y;
            acc[i][2] += z * dv.z;
            acc[i][3] += z * dv.w;
        }
    }
#pragma unroll
    for (int i = 0; i < 8; i++) {
        int j = j0 + ty * 8 + i;
        *(float4*)&g_H[(size_t)j * NA + n0 + tx * 4] =
            make_float4(acc[i][0], acc[i][1], acc[i][2], acc[i][3]);
    }
}

// ---------------------------------------------------------------------------
// OMP: one warp per signal, 4 warps/block. Selected G rows live in SMEM
// (40 KB/block -> 5 blocks/SM, 20 warps/SM). No fp32 divisions anywhere:
// reciprocals of L diagonal are carried (1 rsqrt per iteration).
// ---------------------------------------------------------------------------
__global__ __launch_bounds__(128, 5) void k_omp(float* __restrict__ out) {
    __shared__ float sGrow[4][SP * NA];  // 40960 B
    __shared__ float bsum[4];
    int warp = threadIdx.x >> 5;
    int lane = threadIdx.x & 31;
    int j = blockIdx.x * 4 + warp;
    float* sG = sGrow[warp];

    // load h_bar for this signal: lane holds n = lane + 32*q
    float hbar[16];
    const float* hrow = g_H + (size_t)j * NA;
#pragma unroll
    for (int q = 0; q < 16; q++) hbar[q] = hrow[lane + (q << 5)];

    float L[SP][SP];
    float rinv[SP];  // 1 / L[i][i]
    float x[SP];
    float hb[SP];
    int I[SP];
    unsigned mask16 = 0;

#pragma unroll
    for (int k = 1; k <= SP; k++) {
        // masked argmax of |h_bar - sum_{i<k-1} x_i * G[I_i]| (first-max on tie)
        float bestu = -1.0f;
        int bestn = 0;
        float bhb = 0.0f;
#pragma unroll
        for (int q = 0; q < 16; q++) {
            int n = lane + (q << 5);
            float h = hbar[q];
#pragma unroll
            for (int i = 0; i < k - 1; i++) h -= x[i] * sG[i * NA + n];
            float u = ((mask16 >> q) & 1u) ? 0.0f : fabsf(h);
            if (u > bestu) { bestu = u; bestn = n; bhb = hbar[q]; }
        }
#pragma unroll
        for (int off = 16; off; off >>= 1) {
            float ou = __shfl_xor_sync(0xFFFFFFFFu, bestu, off);
            int on = __shfl_xor_sync(0xFFFFFFFFu, bestn, off);
            float ob = __shfl_xor_sync(0xFFFFFFFFu, bhb, off);
            if (ou > bestu || (ou == bestu && on < bestn)) {
                bestu = ou; bestn = on; bhb = ob;
            }
        }
        I[k - 1] = bestn;
        hb[k - 1] = bhb;
        if ((bestn & 31) == lane) mask16 |= 1u << (bestn >> 5);

        // fetch gv (from already-staged smem rows) before overwriting anything
        float gv[SP];
#pragma unroll
        for (int i = 0; i < SP - 1; i++)
            if (i < k - 1) gv[i] = sG[i * NA + bestn];

        // stage the new atom's G row into smem (coalesced float4)
        {
            const float4* grow4 = (const float4*)(g_G + (size_t)bestn * NA);
            float4* dst4 = (float4*)(sG + (k - 1) * NA);
#pragma unroll
            for (int qq = 0; qq < 4; qq++)
                dst4[qq * 32 + lane] = grow4[qq * 32 + lane];
        }
        __syncwarp();

        // Cholesky-style L update (all lanes redundantly, division-free)
        if (k == 1) {
            L[0][0] = 1.0f;
            rinv[0] = 1.0f;
        } else {
            float w[SP - 1];
            float ss = 0.0f;
#pragma unroll
            for (int i = 0; i < k - 1; i++) {
                float s = gv[i];
#pragma unroll
                for (int j2 = 0; j2 < i; j2++) s -= L[i][j2] * w[j2];
                w[i] = s * rinv[i];
                ss += w[i] * w[i];
            }
#pragma unroll
            for (int j2 = 0; j2 < k - 1; j2++) L[k - 1][j2] = w[j2];
            float v = fmaxf(1.0f - ss, 0.0f);
            float rs = rsqrtf(v);
            L[k - 1][k - 1] = v * rs;  // sqrt(v)
            rinv[k - 1] = rs;          // 1/sqrt(v)
        }

        // y = L^{-1} hb ; x = L^{-T} y   (division-free)
        float y[SP];
#pragma unroll
        for (int i = 0; i < k; i++) {
            float s = hb[i];
#pragma unroll
            for (int j2 = 0; j2 < i; j2++) s -= L[i][j2] * y[j2];
            y[i] = s * rinv[i];
        }
#pragma unroll
        for (int i = k - 1; i >= 0; i--) {
            float s = y[i];
#pragma unroll
            for (int j2 = i + 1; j2 < k; j2++) s -= L[j2][i] * x[j2];
            x[i] = s * rinv[i];
        }
    }

    // reconstruction: recon[m] = sum_i x_i * D[m][I_i]
    float ze0 = g_Zt[j * MD + lane];
    float ze1 = g_Zt[j * MD + 32 + lane];
    float r0 = 0.f, r1 = 0.f;
#pragma unroll
    for (int i = 0; i < SP; i++) {
        const float* dcol = g_Dt + I[i] * MD;
        r0 += x[i] * dcol[lane];
        r1 += x[i] * dcol[32 + lane];
    }

    // z_out = ze + (recon - ze), scattered back to NCHW
    // f = m*32768 + j -> c = f&63, w=(f>>6)&31, h=(f>>11)&31, b=f>>16
#pragma unroll
    for (int p = 0; p < 2; p++) {
        int m = lane + 32 * p;
        float rm = p ? r1 : r0;
        float ze = p ? ze1 : ze0;
        float zo = ze + (rm - ze);
        int f = (m << 15) | j;
        int c = f & 63, ww = (f >> 6) & 31, hh = (f >> 11) & 31, bb = f >> 16;
        out[((bb * 64 + c) * 32 + hh) * 32 + ww] = zo;
    }

    // loss partial: 1.25 * mean((recon - ze)^2)
    float d0 = r0 - ze0, d1 = r1 - ze1;
    float s = d0 * d0 + d1 * d1;
#pragma unroll
    for (int off = 16; off; off >>= 1) s += __shfl_xor_sync(0xFFFFFFFFu, s, off);
    if (lane == 0) bsum[warp] = s;
    __syncthreads();
    if (threadIdx.x == 0) {
        float t = bsum[0] + bsum[1] + bsum[2] + bsum[3];
        atomicAdd(out + LOSS_OFF, t * (1.25f / (float)ZELEMS));
    }

    // scatter the 5 coefficients
    if (lane == 0) {
        float* co = out + COEF_OFF;
        co[(size_t)I[0] * NB + j] = x[0];
        co[(size_t)I[1] * NB + j] = x[1];
        co[(size_t)I[2] * NB + j] = x[2];
        co[(size_t)I[3] * NB + j] = x[3];
        co[(size_t)I[4] * NB + j] = x[4];
    }
}

// ---------------------------------------------------------------------------
extern "C" void kernel_launch(void* const* d_in, const int* in_sizes, int n_in,
                              void* d_out, int out_size) {
    const float* ze = (const float*)d_in[0];  // (32, 64, 32, 32)
    const float* D = (const float*)d_in[1];   // (64, 512)
    float* out = (float*)d_out;

    int ztail = out_size - LOSS_OFF;  // loss + coefficients
    k_prep<<<4096, 256>>>(out, ztail, D);
    k_scatter<<<(ZELEMS + 255) / 256, 256>>>(ze);
    k_gram<<<dim3(16, 16), 256>>>(D);
    k_gemm<<<dim3(NB / 128, NA / 64), 256>>>(D);
    k_omp<<<NB / 4, 128>>>(out);
}

// round 5
// speedup vs baseline: 1.1749x; 1.0677x over previous
#include <cuda_runtime.h>
#include <cuda_bf16.h>
#include <cstdint>

// Problem constants
#define NB 32768   // number of signals (B)
#define NA 512     // number of atoms (N)
#define MD 64      // embedding dim (M)
#define SP 5       // sparsity
#define ZELEMS 2097152        // 32*64*32*32
#define LOSS_OFF ZELEMS       // loss scalar offset in d_out
#define COEF_OFF (ZELEMS + 1) // coefficients offset in d_out

// Scratch (static __device__ — no allocation allowed)
__device__ float g_Zt[NB * MD];   // Z transposed: [j][m], 8 MB
__device__ float g_H[NB * NA];    // h_bar: [j][n], 64 MB (L2-resident)
__device__ float g_G[NA * NA];    // Gram D^T D, 1 MB
__device__ float g_Dt[NA * MD];   // D transposed: [n][m], 128 KB
// bf16 3-way-split operands, pre-swizzled (SW128-style row^bank) rows of 128 B
// A: per 128-row j-tile, 16 KB each tile (128 rows x 64 bf16)
__device__ __align__(16) __nv_bfloat16 g_A[3][NB * MD];
// B: dictionary [n][k] K-major, 512 rows x 128 B = 64 KB per split
__device__ __align__(16) __nv_bfloat16 g_B[3][NA * MD];

__host__ __device__ __forceinline__ uint32_t sw128(uint32_t o) {
    return o ^ ((o >> 3) & 0x70);
}

__device__ __forceinline__ uint32_t smem_u32(const void* p) {
    uint32_t a;
    asm("{ .reg .u64 t; cvta.to.shared.u64 t, %1; cvt.u32.u64 %0, t; }"
        : "=r"(a) : "l"(p));
    return a;
}
// swizzled smem address for row-major 128B rows
__device__ __forceinline__ uint32_t swaddr(uint32_t base, int row, int colbyte) {
    uint32_t o = (uint32_t)(row * 128 + colbyte);
    return base + (o ^ ((uint32_t)(row & 7) << 4));
}

// ---------------------------------------------------------------------------
// Zero loss+coef region of d_out, transpose D -> Dt, build split B operands
// ---------------------------------------------------------------------------
__global__ void k_prep(float* __restrict__ out, int nfloats,
                       const float* __restrict__ D) {
    int tid = blockIdx.x * blockDim.x + threadIdx.x;
    float4* p = (float4*)(out + LOSS_OFF);
    int n4 = nfloats >> 2;
    for (int i = tid; i < n4; i += gridDim.x * blockDim.x)
        p[i] = make_float4(0.f, 0.f, 0.f, 0.f);
    if (blockIdx.x == 0 && threadIdx.x < (nfloats & 3))
        out[LOSS_OFF + (n4 << 2) + threadIdx.x] = 0.f;
    if (tid < MD * NA) {
        int m = tid >> 9;
        int n = tid & (NA - 1);
        float v = D[tid];
        g_Dt[n * MD + m] = v;
        __nv_bfloat16 bh = __float2bfloat16(v);
        float r1 = v - __bfloat162float(bh);
        __nv_bfloat16 bm = __float2bfloat16(r1);
        float r2 = r1 - __bfloat162float(bm);
        __nv_bfloat16 bl = __float2bfloat16(r2);
        uint32_t so = sw128((uint32_t)(n * 128 + m * 2));
        *(__nv_bfloat16*)((char*)g_B[0] + so) = bh;
        *(__nv_bfloat16*)((char*)g_B[1] + so) = bm;
        *(__nv_bfloat16*)((char*)g_B[2] + so) = bl;
    }
}

// ---------------------------------------------------------------------------
// Scatter z_e (NCHW) -> Zt[j][m] replicating the reference's permute+reshape
// ---------------------------------------------------------------------------
__global__ void k_scatter(const float* __restrict__ ze) {
    int g = blockIdx.x * blockDim.x + threadIdx.x;
    if (g >= ZELEMS) return;
    float v = ze[g];
    int b = g >> 16;
    int c = (g >> 10) & 63;
    int h = (g >> 5) & 31;
    int w = g & 31;
    int f = ((((b << 5) | h) << 5) | w) << 6 | c;
    g_Zt[(f & (NB - 1)) * MD + (f >> 15)] = v;
}

// ---------------------------------------------------------------------------
// Split Zt into bf16 h/m/l swizzled 128-row tiles (A operand).
// ---------------------------------------------------------------------------
__global__ void k_asplit() {
    int idx = blockIdx.x * blockDim.x + threadIdx.x;  // NB*8 total
    if (idx >= NB * 8) return;
    int j = idx >> 3, grp = idx & 7;
    const float4* z4 = (const float4*)(g_Zt + j * MD + grp * 8);
    float4 a = z4[0], b = z4[1];
    float v[8] = {a.x, a.y, a.z, a.w, b.x, b.y, b.z, b.w};
    unsigned short hs[8], ms[8], ls[8];
#pragma unroll
    for (int i = 0; i < 8; i++) {
        __nv_bfloat16 bh = __float2bfloat16(v[i]);
        float r1 = v[i] - __bfloat162float(bh);
        __nv_bfloat16 bm = __float2bfloat16(r1);
        float r2 = r1 - __bfloat162float(bm);
        __nv_bfloat16 bl = __float2bfloat16(r2);
        hs[i] = __bfloat16_as_ushort(bh);
        ms[i] = __bfloat16_as_ushort(bm);
        ls[i] = __bfloat16_as_ushort(bl);
    }
    int tile = j >> 7, r = j & 127;
    uint32_t so = sw128((uint32_t)(r * 128 + grp * 16));
    size_t off = (size_t)tile * 16384 + so;
    uint4 ph = make_uint4(hs[0] | (hs[1] << 16), hs[2] | (hs[3] << 16),
                          hs[4] | (hs[5] << 16), hs[6] | (hs[7] << 16));
    uint4 pm = make_uint4(ms[0] | (ms[1] << 16), ms[2] | (ms[3] << 16),
                          ms[4] | (ms[5] << 16), ms[6] | (ms[7] << 16));
    uint4 pl = make_uint4(ls[0] | (ls[1] << 16), ls[2] | (ls[3] << 16),
                          ls[4] | (ls[5] << 16), ls[6] | (ls[7] << 16));
    *(uint4*)((char*)g_A[0] + off) = ph;
    *(uint4*)((char*)g_A[1] + off) = pm;
    *(uint4*)((char*)g_A[2] + off) = pl;
}

// ---------------------------------------------------------------------------
// Gram matrix G[a][b] = sum_m D[m][a]*D[m][b]. 32x32 tile per block.
// ---------------------------------------------------------------------------
__global__ void k_gram(const float* __restrict__ D) {
    __shared__ float Da[32 * 65];
    __shared__ float Db[32 * 65];
    int a0 = blockIdx.y * 32, b0 = blockIdx.x * 32;
    int t = threadIdx.x;  // 256
#pragma unroll
    for (int it = 0; it < 8; it++) {
        int e = t + it * 256;
        int aa = e & 31, m = e >> 5;
        Da[aa * 65 + m] = D[m * NA + a0 + aa];
        Db[aa * 65 + m] = D[m * NA + b0 + aa];
    }
    __syncthreads();
    int tb = t & 15, ta = t >> 4;
    float acc[2][2] = {};
#pragma unroll
    for (int m = 0; m < MD; m++) {
        float a0v = Da[(2 * ta) * 65 + m];
        float a1v = Da[(2 * ta + 1) * 65 + m];
        float b0v = Db[(2 * tb) * 65 + m];
        float b1v = Db[(2 * tb + 1) * 65 + m];
        acc[0][0] += a0v * b0v; acc[0][1] += a0v * b1v;
        acc[1][0] += a1v * b0v; acc[1][1] += a1v * b1v;
    }
#pragma unroll
    for (int i = 0; i < 2; i++)
#pragma unroll
        for (int l = 0; l < 2; l++)
            g_G[(a0 + 2 * ta + i) * NA + (b0 + 2 * tb + l)] = acc[i][l];
}

// ---------------------------------------------------------------------------
// HMMA GEMM via mma.sync m16n8k16 bf16, 3-way split (6 products).
// Block: 128 j x 128 n, K=64 resident. 8 warps: warpm=wid&3 (32 rows),
// warpn=wid>>2 (64 cols). Per warp: 2x8 m16n8 accum tiles.
// Smem: 3x16KB A + 3x16KB B = 96 KB -> 2 blocks/SM.
// ---------------------------------------------------------------------------
__global__ __launch_bounds__(256) void k_gemm_mma() {
    extern __shared__ char smem[];
    uint32_t sb = smem_u32(smem);
    int tid = threadIdx.x;
    int wid = tid >> 5, lane = tid & 31;
    int j0 = blockIdx.x * 128;
    int n0 = blockIdx.y * 128;

    // fill A (3 x 16 KB) and B (3 x 16 KB) — pre-swizzled, linear copy
#pragma unroll
    for (int p = 0; p < 3; p++) {
        const uint4* srcA = (const uint4*)g_A[p] + blockIdx.x * 1024;
        uint4* dstA = (uint4*)(smem + p * 16384);
        const uint4* srcB = (const uint4*)g_B[p] + blockIdx.y * 1024;
        uint4* dstB = (uint4*)(smem + 49152 + p * 16384);
#pragma unroll
        for (int it = 0; it < 4; it++) {
            dstA[tid + it * 256] = srcA[tid + it * 256];
            dstB[tid + it * 256] = srcB[tid + it * 256];
        }
    }
    __syncthreads();

    int warpm = wid & 3, warpn = wid >> 2;
    float acc[2][8][4] = {};

    // products small -> large: (Ah,Bl),(Al,Bh),(Am,Bm),(Ah,Bm),(Am,Bh),(Ah,Bh)
    const int PA[6] = {0, 2, 1, 0, 1, 0};
    const int PB[6] = {2, 0, 1, 1, 0, 0};

#pragma unroll
    for (int pr = 0; pr < 6; pr++) {
        uint32_t aBase = sb + PA[pr] * 16384;
        uint32_t bBase = sb + 49152 + PB[pr] * 16384;
#pragma unroll
        for (int k = 0; k < 64; k += 16) {
            // A fragments for mt = 0,1
            uint32_t a[2][4];
#pragma unroll
            for (int mt = 0; mt < 2; mt++) {
                int arow = warpm * 32 + mt * 16 + (lane & 15);
                int acol = k + ((lane >> 4) << 3);
                uint32_t addr = swaddr(aBase, arow, acol * 2);
                asm volatile(
                    "ldmatrix.sync.aligned.m8n8.x4.shared.b16 {%0,%1,%2,%3}, [%4];"
                    : "=r"(a[mt][0]), "=r"(a[mt][1]), "=r"(a[mt][2]), "=r"(a[mt][3])
                    : "r"(addr));
            }
            // B fragments for 8 n-tiles (pairs via x4)
            uint32_t b[8][2];
#pragma unroll
            for (int np = 0; np < 4; np++) {
                int brow = warpn * 64 + np * 16 + ((lane >> 4) << 3) + (lane & 7);
                int bcol = k + (((lane >> 3) & 1) << 3);
                uint32_t addr = swaddr(bBase, brow, bcol * 2);
                uint32_t r0, r1, r2, r3;
                asm volatile(
                    "ldmatrix.sync.aligned.m8n8.x4.shared.b16 {%0,%1,%2,%3}, [%4];"
                    : "=r"(r0), "=r"(r1), "=r"(r2), "=r"(r3) : "r"(addr));
                b[np * 2][0] = r0;     b[np * 2][1] = r1;
                b[np * 2 + 1][0] = r2; b[np * 2 + 1][1] = r3;
            }
#pragma unroll
            for (int mt = 0; mt < 2; mt++)
#pragma unroll
                for (int nt = 0; nt < 8; nt++) {
                    asm volatile(
                        "mma.sync.aligned.m16n8k16.row.col.f32.bf16.bf16.f32 "
                        "{%0,%1,%2,%3}, {%4,%5,%6,%7}, {%8,%9}, {%0,%1,%2,%3};"
                        : "+f"(acc[mt][nt][0]), "+f"(acc[mt][nt][1]),
                          "+f"(acc[mt][nt][2]), "+f"(acc[mt][nt][3])
                        : "r"(a[mt][0]), "r"(a[mt][1]), "r"(a[mt][2]), "r"(a[mt][3]),
                          "r"(b[nt][0]), "r"(b[nt][1]));
                }
        }
    }

    // epilogue: C fragment rows lane/4 (+8), cols (lane%4)*2 (+1)
    int rbase = j0 + warpm * 32 + (lane >> 2);
    int cbase = n0 + warpn * 64 + (lane & 3) * 2;
#pragma unroll
    for (int mt = 0; mt < 2; mt++)
#pragma unroll
        for (int nt = 0; nt < 8; nt++) {
            int r = rbase + mt * 16;
            int c = cbase + nt * 8;
            *(float2*)&g_H[(size_t)r * NA + c] =
                make_float2(acc[mt][nt][0], acc[mt][nt][1]);
            *(float2*)&g_H[(size_t)(r + 8) * NA + c] =
                make_float2(acc[mt][nt][2], acc[mt][nt][3]);
        }
}

// ---------------------------------------------------------------------------
// OMP: one warp per signal, 4 warps/block, G rows in SMEM, division-free.
// ---------------------------------------------------------------------------
__global__ __launch_bounds__(128, 5) void k_omp(float* __restrict__ out) {
    __shared__ float sGrow[4][SP * NA];  // 40960 B
    __shared__ float bsum[4];
    int warp = threadIdx.x >> 5;
    int lane = threadIdx.x & 31;
    int j = blockIdx.x * 4 + warp;
    float* sG = sGrow[warp];

    float hbar[16];
    const float* hrow = g_H + (size_t)j * NA;
#pragma unroll
    for (int q = 0; q < 16; q++) hbar[q] = hrow[lane + (q << 5)];

    float L[SP][SP];
    float rinv[SP];
    float x[SP];
    float hb[SP];
    int I[SP];
    unsigned mask16 = 0;

#pragma unroll
    for (int k = 1; k <= SP; k++) {
        float bestu = -1.0f;
        int bestn = 0;
        float bhb = 0.0f;
#pragma unroll
        for (int q = 0; q < 16; q++) {
            int n = lane + (q << 5);
            float h = hbar[q];
#pragma unroll
            for (int i = 0; i < k - 1; i++) h -= x[i] * sG[i * NA + n];
            float u = ((mask16 >> q) & 1u) ? 0.0f : fabsf(h);
            if (u > bestu) { bestu = u; bestn = n; bhb = hbar[q]; }
        }
#pragma unroll
        for (int off = 16; off; off >>= 1) {
            float ou = __shfl_xor_sync(0xFFFFFFFFu, bestu, off);
            int on = __shfl_xor_sync(0xFFFFFFFFu, bestn, off);
            float ob = __shfl_xor_sync(0xFFFFFFFFu, bhb, off);
            if (ou > bestu || (ou == bestu && on < bestn)) {
                bestu = ou; bestn = on; bhb = ob;
            }
        }
        I[k - 1] = bestn;
        hb[k - 1] = bhb;
        if ((bestn & 31) == lane) mask16 |= 1u << (bestn >> 5);

        float gv[SP];
#pragma unroll
        for (int i = 0; i < SP - 1; i++)
            if (i < k - 1) gv[i] = sG[i * NA + bestn];

        {
            const float4* grow4 = (const float4*)(g_G + (size_t)bestn * NA);
            float4* dst4 = (float4*)(sG + (k - 1) * NA);
#pragma unroll
            for (int qq = 0; qq < 4; qq++)
                dst4[qq * 32 + lane] = grow4[qq * 32 + lane];
        }
        __syncwarp();

        if (k == 1) {
            L[0][0] = 1.0f;
            rinv[0] = 1.0f;
        } else {
            float w[SP - 1];
            float ss = 0.0f;
#pragma unroll
            for (int i = 0; i < k - 1; i++) {
                float s = gv[i];
#pragma unroll
                for (int j2 = 0; j2 < i; j2++) s -= L[i][j2] * w[j2];
                w[i] = s * rinv[i];
                ss += w[i] * w[i];
            }
#pragma unroll
            for (int j2 = 0; j2 < k - 1; j2++) L[k - 1][j2] = w[j2];
            float v = fmaxf(1.0f - ss, 0.0f);
            float rs = rsqrtf(v);
            L[k - 1][k - 1] = v * rs;
            rinv[k - 1] = rs;
        }

        float y[SP];
#pragma unroll
        for (int i = 0; i < k; i++) {
            float s = hb[i];
#pragma unroll
            for (int j2 = 0; j2 < i; j2++) s -= L[i][j2] * y[j2];
            y[i] = s * rinv[i];
        }
#pragma unroll
        for (int i = k - 1; i >= 0; i--) {
            float s = y[i];
#pragma unroll
            for (int j2 = i + 1; j2 < k; j2++) s -= L[j2][i] * x[j2];
            x[i] = s * rinv[i];
        }
    }

    float ze0 = g_Zt[j * MD + lane];
    float ze1 = g_Zt[j * MD + 32 + lane];
    float r0 = 0.f, r1 = 0.f;
#pragma unroll
    for (int i = 0; i < SP; i++) {
        const float* dcol = g_Dt + I[i] * MD;
        r0 += x[i] * dcol[lane];
        r1 += x[i] * dcol[32 + lane];
    }

#pragma unroll
    for (int p = 0; p < 2; p++) {
        int m = lane + 32 * p;
        float rm = p ? r1 : r0;
        float ze = p ? ze1 : ze0;
        float zo = ze + (rm - ze);
        int f = (m << 15) | j;
        int c = f & 63, ww = (f >> 6) & 31, hh = (f >> 11) & 31, bb = f >> 16;
        out[((bb * 64 + c) * 32 + hh) * 32 + ww] = zo;
    }

    float d0 = r0 - ze0, d1 = r1 - ze1;
    float s = d0 * d0 + d1 * d1;
#pragma unroll
    for (int off = 16; off; off >>= 1) s += __shfl_xor_sync(0xFFFFFFFFu, s, off);
    if (lane == 0) bsum[warp] = s;
    __syncthreads();
    if (threadIdx.x == 0) {
        float t = bsum[0] + bsum[1] + bsum[2] + bsum[3];
        atomicAdd(out + LOSS_OFF, t * (1.25f / (float)ZELEMS));
    }

    if (lane == 0) {
        float* co = out + COEF_OFF;
        co[(size_t)I[0] * NB + j] = x[0];
        co[(size_t)I[1] * NB + j] = x[1];
        co[(size_t)I[2] * NB + j] = x[2];
        co[(size_t)I[3] * NB + j] = x[3];
        co[(size_t)I[4] * NB + j] = x[4];
    }
}

// ---------------------------------------------------------------------------
extern "C" void kernel_launch(void* const* d_in, const int* in_sizes, int n_in,
                              void* d_out, int out_size) {
    const float* ze = (const float*)d_in[0];  // (32, 64, 32, 32)
    const float* D = (const float*)d_in[1];   // (64, 512)
    float* out = (float*)d_out;

    cudaFuncSetAttribute(k_gemm_mma,
                         cudaFuncAttributeMaxDynamicSharedMemorySize, 98304);

    int ztail = out_size - LOSS_OFF;  // loss + coefficients
    k_prep<<<4096, 256>>>(out, ztail, D);
    k_scatter<<<(ZELEMS + 255) / 256, 256>>>(ze);
    k_asplit<<<(NB * 8 + 255) / 256, 256>>>();
    k_gram<<<dim3(16, 16), 256>>>(D);
    k_gemm_mma<<<dim3(NB / 128, NA / 128), 256, 98304>>>();
    k_omp<<<NB / 4, 128>>>(out);
}

// round 7
// speedup vs baseline: 1.3282x; 1.1305x over previous
#include <cuda_runtime.h>
#include <cuda_bf16.h>
#include <cstdint>

// Problem constants
#define NB 32768   // number of signals (B)
#define NA 512     // number of atoms (N)
#define MD 64      // embedding dim (M)
#define SP 5       // sparsity
#define ZELEMS 2097152        // 32*64*32*32
#define LOSS_OFF ZELEMS       // loss scalar offset in d_out
#define COEF_OFF (ZELEMS + 1) // coefficients offset in d_out

// Scratch (static __device__ — no allocation allowed)
__device__ float g_Zt[NB * MD];   // Z transposed: [j][m], 8 MB
__device__ float g_H[NB * NA];    // h_bar: [j][n], 64 MB (keep L2-warm)
__device__ float g_G[NA * NA];    // Gram D^T D, 1 MB
__device__ float g_Dt[NA * MD];   // D transposed: [n][m], 128 KB
// bf16 3-way-split operands, pre-swizzled rows of 128 B
__device__ __align__(16) __nv_bfloat16 g_A[3][NB * MD];
__device__ __align__(16) __nv_bfloat16 g_B[3][NA * MD];

__host__ __device__ __forceinline__ uint32_t sw128(uint32_t o) {
    return o ^ ((o >> 3) & 0x70);
}
__device__ __forceinline__ uint32_t smem_u32(const void* p) {
    uint32_t a;
    asm("{ .reg .u64 t; cvta.to.shared.u64 t, %1; cvt.u32.u64 %0, t; }"
        : "=r"(a) : "l"(p));
    return a;
}
__device__ __forceinline__ uint32_t swaddr(uint32_t base, int row, int colbyte) {
    uint32_t o = (uint32_t)(row * 128 + colbyte);
    return base + (o ^ ((uint32_t)(row & 7) << 4));
}

// ---------------------------------------------------------------------------
// k_prep: zero loss+coef (streaming stores), Dt transpose + B split,
// and (blocks < 256) the Gram matrix tiles.
// ---------------------------------------------------------------------------
__global__ void k_prep(float* __restrict__ out, int nfloats,
                       const float* __restrict__ D) {
    __shared__ float Da[32 * 65];
    __shared__ float Db[32 * 65];
    int tid = blockIdx.x * blockDim.x + threadIdx.x;

    float4* p = (float4*)(out + LOSS_OFF);
    int n4 = nfloats >> 2;
    float4 z4 = make_float4(0.f, 0.f, 0.f, 0.f);
    for (int i = tid; i < n4; i += gridDim.x * blockDim.x) __stcs(p + i, z4);
    if (blockIdx.x == 0 && threadIdx.x < (nfloats & 3))
        out[LOSS_OFF + (n4 << 2) + threadIdx.x] = 0.f;

    if (tid < MD * NA) {
        int m = tid >> 9;
        int n = tid & (NA - 1);
        float v = D[tid];
        g_Dt[n * MD + m] = v;
        __nv_bfloat16 bh = __float2bfloat16(v);
        float r1 = v - __bfloat162float(bh);
        __nv_bfloat16 bm = __float2bfloat16(r1);
        float r2 = r1 - __bfloat162float(bm);
        __nv_bfloat16 bl = __float2bfloat16(r2);
        uint32_t so = sw128((uint32_t)(n * 128 + m * 2));
        *(__nv_bfloat16*)((char*)g_B[0] + so) = bh;
        *(__nv_bfloat16*)((char*)g_B[1] + so) = bm;
        *(__nv_bfloat16*)((char*)g_B[2] + so) = bl;
    }

    // Gram tiles on blocks [0, 256)
    if (blockIdx.x < 256) {
        int a0 = (blockIdx.x >> 4) * 32, b0 = (blockIdx.x & 15) * 32;
        int t = threadIdx.x;  // 256
#pragma unroll
        for (int it = 0; it < 8; it++) {
            int e = t + it * 256;
            int aa = e & 31, m = e >> 5;
            Da[aa * 65 + m] = D[m * NA + a0 + aa];
            Db[aa * 65 + m] = D[m * NA + b0 + aa];
        }
        __syncthreads();
        int tb = t & 15, ta = t >> 4;
        float acc[2][2] = {};
#pragma unroll
        for (int m = 0; m < MD; m++) {
            float a0v = Da[(2 * ta) * 65 + m];
            float a1v = Da[(2 * ta + 1) * 65 + m];
            float b0v = Db[(2 * tb) * 65 + m];
            float b1v = Db[(2 * tb + 1) * 65 + m];
            acc[0][0] += a0v * b0v; acc[0][1] += a0v * b1v;
            acc[1][0] += a1v * b0v; acc[1][1] += a1v * b1v;
        }
#pragma unroll
        for (int i = 0; i < 2; i++)
#pragma unroll
            for (int l = 0; l < 2; l++)
                g_G[(a0 + 2 * ta + i) * NA + (b0 + 2 * tb + l)] = acc[i][l];
    }
}

// ---------------------------------------------------------------------------
// Fused scatter + bf16 split (FIXED indexing).
// Inverse map: for f = m*32768+j,  g = (m>>1)<<16 | (j&63)<<10 | (m&1)<<9
//                                      | ((j>>11)&15)<<5 | ((j>>6)&31)
// Thread mapping: lane = (j>>6)&31 so warp reads are 128B-contiguous in ze.
//   t: [jhi4 (4b)][jlow6 (6b)][grp (3b)][lane (5b)]
// ---------------------------------------------------------------------------
__global__ void k_ssplit(const float* __restrict__ ze) {
    int t = blockIdx.x * blockDim.x + threadIdx.x;  // 262144
    int lane = t & 31;
    int grp = (t >> 5) & 7;         // m-group of 8
    int jlow6 = (t >> 8) & 63;      // c
    int jhi4 = t >> 14;             // j>>11
    int j = (jhi4 << 11) | (lane << 6) | jlow6;

    int base_g = ((grp * 4) << 16) | (jlow6 << 10) | (jhi4 << 5) | lane;
    float v[8];
#pragma unroll
    for (int e = 0; e < 8; e++)
        v[e] = __ldcs(ze + base_g + ((e >> 1) << 16) + ((e & 1) << 9));

    float4* zt4 = (float4*)(g_Zt + j * MD + grp * 8);
    zt4[0] = make_float4(v[0], v[1], v[2], v[3]);
    zt4[1] = make_float4(v[4], v[5], v[6], v[7]);

    unsigned short hs[8], ms[8], ls[8];
#pragma unroll
    for (int i = 0; i < 8; i++) {
        __nv_bfloat16 bh = __float2bfloat16(v[i]);
        float r1 = v[i] - __bfloat162float(bh);
        __nv_bfloat16 bm = __float2bfloat16(r1);
        float r2 = r1 - __bfloat162float(bm);
        __nv_bfloat16 bl = __float2bfloat16(r2);
        hs[i] = __bfloat16_as_ushort(bh);
        ms[i] = __bfloat16_as_ushort(bm);
        ls[i] = __bfloat16_as_ushort(bl);
    }
    int tile = j >> 7, r = j & 127;
    uint32_t so = sw128((uint32_t)(r * 128 + grp * 16));
    size_t off = (size_t)tile * 16384 + so;
    *(uint4*)((char*)g_A[0] + off) =
        make_uint4(hs[0] | (hs[1] << 16), hs[2] | (hs[3] << 16),
                   hs[4] | (hs[5] << 16), hs[6] | (hs[7] << 16));
    *(uint4*)((char*)g_A[1] + off) =
        make_uint4(ms[0] | (ms[1] << 16), ms[2] | (ms[3] << 16),
                   ms[4] | (ms[5] << 16), ms[6] | (ms[7] << 16));
    *(uint4*)((char*)g_A[2] + off) =
        make_uint4(ls[0] | (ls[1] << 16), ls[2] | (ls[3] << 16),
                   ls[4] | (ls[5] << 16), ls[6] | (ls[7] << 16));
}

// ---------------------------------------------------------------------------
// HMMA GEMM, 3-way bf16 split, gray-code product order (1 operand reload/step).
// Block: 128 j x 128 n, K=64 resident. 8 warps, 2x8 m16n8 tiles each.
// ---------------------------------------------------------------------------
__global__ __launch_bounds__(256, 2) void k_gemm_mma() {
    extern __shared__ char smem[];
    uint32_t sb = smem_u32(smem);
    int tid = threadIdx.x;
    int wid = tid >> 5, lane = tid & 31;
    int j0 = blockIdx.x * 128;
    int n0 = blockIdx.y * 128;

#pragma unroll
    for (int p = 0; p < 3; p++) {
        const uint4* srcA = (const uint4*)g_A[p] + blockIdx.x * 1024;
        uint4* dstA = (uint4*)(smem + p * 16384);
        const uint4* srcB = (const uint4*)g_B[p] + blockIdx.y * 1024;
        uint4* dstB = (uint4*)(smem + 49152 + p * 16384);
#pragma unroll
        for (int it = 0; it < 4; it++) {
            dstA[tid + it * 256] = srcA[tid + it * 256];
            dstB[tid + it * 256] = srcB[tid + it * 256];
        }
    }
    __syncthreads();

    int warpm = wid & 3, warpn = wid >> 2;
    float acc[2][8][4] = {};

    // gray-code order: (h,l)(h,m)(m,m)(m,h)(h,h)(l,h) — one operand changes/step
    const int GA[6] = {0, 0, 1, 1, 0, 2};
    const int GB[6] = {2, 1, 1, 0, 0, 0};

#pragma unroll
    for (int k = 0; k < 64; k += 16) {
        uint32_t a[2][4];
        uint32_t b[8][2];
#pragma unroll
        for (int s = 0; s < 6; s++) {
            if (s == 0 || GA[s] != GA[s - 1]) {
                uint32_t aBase = sb + GA[s] * 16384;
#pragma unroll
                for (int mt = 0; mt < 2; mt++) {
                    int arow = warpm * 32 + mt * 16 + (lane & 15);
                    int acol = k + ((lane >> 4) << 3);
                    uint32_t addr = swaddr(aBase, arow, acol * 2);
                    asm volatile(
                        "ldmatrix.sync.aligned.m8n8.x4.shared.b16 {%0,%1,%2,%3}, [%4];"
                        : "=r"(a[mt][0]), "=r"(a[mt][1]), "=r"(a[mt][2]),
                          "=r"(a[mt][3])
                        : "r"(addr));
                }
            }
            if (s == 0 || GB[s] != GB[s - 1]) {
                uint32_t bBase = sb + 49152 + GB[s] * 16384;
#pragma unroll
                for (int np = 0; np < 4; np++) {
                    int brow = warpn * 64 + np * 16 + ((lane >> 4) << 3) + (lane & 7);
                    int bcol = k + (((lane >> 3) & 1) << 3);
                    uint32_t addr = swaddr(bBase, brow, bcol * 2);
                    uint32_t r0, r1, r2, r3;
                    asm volatile(
                        "ldmatrix.sync.aligned.m8n8.x4.shared.b16 {%0,%1,%2,%3}, [%4];"
                        : "=r"(r0), "=r"(r1), "=r"(r2), "=r"(r3) : "r"(addr));
                    b[np * 2][0] = r0;     b[np * 2][1] = r1;
                    b[np * 2 + 1][0] = r2; b[np * 2 + 1][1] = r3;
                }
            }
#pragma unroll
            for (int mt = 0; mt < 2; mt++)
#pragma unroll
                for (int nt = 0; nt < 8; nt++) {
                    asm volatile(
                        "mma.sync.aligned.m16n8k16.row.col.f32.bf16.bf16.f32 "
                        "{%0,%1,%2,%3}, {%4,%5,%6,%7}, {%8,%9}, {%0,%1,%2,%3};"
                        : "+f"(acc[mt][nt][0]), "+f"(acc[mt][nt][1]),
                          "+f"(acc[mt][nt][2]), "+f"(acc[mt][nt][3])
                        : "r"(a[mt][0]), "r"(a[mt][1]), "r"(a[mt][2]),
                          "r"(a[mt][3]), "r"(b[nt][0]), "r"(b[nt][1]));
                }
        }
    }

    int rbase = j0 + warpm * 32 + (lane >> 2);
    int cbase = n0 + warpn * 64 + (lane & 3) * 2;
#pragma unroll
    for (int mt = 0; mt < 2; mt++)
#pragma unroll
        for (int nt = 0; nt < 8; nt++) {
            int r = rbase + mt * 16;
            int c = cbase + nt * 8;
            *(float2*)&g_H[(size_t)r * NA + c] =
                make_float2(acc[mt][nt][0], acc[mt][nt][1]);
            *(float2*)&g_H[(size_t)(r + 8) * NA + c] =
                make_float2(acc[mt][nt][2], acc[mt][nt][3]);
        }
}

// ---------------------------------------------------------------------------
// OMP: one warp per signal, float4 layout (n = lane*4 + 128q + e), G rows in
// SMEM, division-free solves. Owner-lane check FIXED: (bestn>>2)&31.
// ---------------------------------------------------------------------------
__global__ __launch_bounds__(128, 5) void k_omp(float* __restrict__ out) {
    __shared__ float sGrow[4][SP * NA];  // 40960 B
    __shared__ float bsum[4];
    int warp = threadIdx.x >> 5;
    int lane = threadIdx.x & 31;
    int j = blockIdx.x * 4 + warp;
    float* sG = sGrow[warp];
    const float4* sG4 = (const float4*)sG;

    float4 hb4[4];
    const float4* hrow4 = (const float4*)(g_H + (size_t)j * NA);
#pragma unroll
    for (int q = 0; q < 4; q++) hb4[q] = hrow4[lane + 32 * q];

    float L[SP][SP];
    float rinv[SP];
    float x[SP];
    float hb[SP];
    int I[SP];
    unsigned mask16 = 0;

#pragma unroll
    for (int k = 1; k <= SP; k++) {
        // masked argmax of |h| (first-max tie-break; within-lane scan is
        // n-ascending so plain > keeps the smallest n)
        float bestu = -1.0f;
        int bestn = 0;
        float bhb = 0.0f;
#pragma unroll
        for (int q = 0; q < 4; q++) {
            float4 h4 = hb4[q];
#pragma unroll
            for (int i = 0; i < k - 1; i++) {
                float4 g4 = sG4[i * 128 + lane + 32 * q];
                h4.x -= x[i] * g4.x; h4.y -= x[i] * g4.y;
                h4.z -= x[i] * g4.z; h4.w -= x[i] * g4.w;
            }
            float hv[4] = {h4.x, h4.y, h4.z, h4.w};
            float hbv[4] = {hb4[q].x, hb4[q].y, hb4[q].z, hb4[q].w};
#pragma unroll
            for (int e = 0; e < 4; e++) {
                int bit = q * 4 + e;
                float u = ((mask16 >> bit) & 1u) ? 0.0f : fabsf(hv[e]);
                if (u > bestu) {
                    bestu = u;
                    bestn = lane * 4 + 128 * q + e;
                    bhb = hbv[e];
                }
            }
        }
#pragma unroll
        for (int off = 16; off; off >>= 1) {
            float ou = __shfl_xor_sync(0xFFFFFFFFu, bestu, off);
            int on = __shfl_xor_sync(0xFFFFFFFFu, bestn, off);
            float ob = __shfl_xor_sync(0xFFFFFFFFu, bhb, off);
            if (ou > bestu || (ou == bestu && on < bestn)) {
                bestu = ou; bestn = on; bhb = ob;
            }
        }
        I[k - 1] = bestn;
        hb[k - 1] = bhb;
        if (((bestn >> 2) & 31) == lane)  // owning lane (FIXED)
            mask16 |= 1u << (((bestn >> 7) << 2) | (bestn & 3));

        float gv[SP];
#pragma unroll
        for (int i = 0; i < SP - 1; i++)
            if (i < k - 1) gv[i] = sG[i * NA + bestn];

        {
            const float4* grow4 = (const float4*)(g_G + (size_t)bestn * NA);
            float4* dst4 = (float4*)(sG + (k - 1) * NA);
#pragma unroll
            for (int qq = 0; qq < 4; qq++)
                dst4[qq * 32 + lane] = grow4[qq * 32 + lane];
        }
        __syncwarp();

        if (k == 1) {
            L[0][0] = 1.0f;
            rinv[0] = 1.0f;
        } else {
            float w[SP - 1];
            float ss = 0.0f;
#pragma unroll
            for (int i = 0; i < k - 1; i++) {
                float s = gv[i];
#pragma unroll
                for (int j2 = 0; j2 < i; j2++) s -= L[i][j2] * w[j2];
                w[i] = s * rinv[i];
                ss += w[i] * w[i];
            }
#pragma unroll
            for (int j2 = 0; j2 < k - 1; j2++) L[k - 1][j2] = w[j2];
            float v = fmaxf(1.0f - ss, 0.0f);
            float rs = rsqrtf(v);
            L[k - 1][k - 1] = v * rs;
            rinv[k - 1] = rs;
        }

        float y[SP];
#pragma unroll
        for (int i = 0; i < k; i++) {
            float s = hb[i];
#pragma unroll
            for (int j2 = 0; j2 < i; j2++) s -= L[i][j2] * y[j2];
            y[i] = s * rinv[i];
        }
#pragma unroll
        for (int i = k - 1; i >= 0; i--) {
            float s = y[i];
#pragma unroll
            for (int j2 = i + 1; j2 < k; j2++) s -= L[j2][i] * x[j2];
            x[i] = s * rinv[i];
        }
    }

    float ze0 = g_Zt[j * MD + lane];
    float ze1 = g_Zt[j * MD + 32 + lane];
    float r0 = 0.f, r1 = 0.f;
#pragma unroll
    for (int i = 0; i < SP; i++) {
        const float* dcol = g_Dt + I[i] * MD;
        r0 += x[i] * dcol[lane];
        r1 += x[i] * dcol[32 + lane];
    }

    // z_out scattered back to NCHW: c=f&63, w=(f>>6)&31, h=(f>>11)&31, b=f>>16
#pragma unroll
    for (int p = 0; p < 2; p++) {
        int m = lane + 32 * p;
        float rm = p ? r1 : r0;
        float ze = p ? ze1 : ze0;
        float zo = ze + (rm - ze);
        int f = (m << 15) | j;
        int c = f & 63, ww = (f >> 6) & 31, hh = (f >> 11) & 31, bb = f >> 16;
        __stcs(&out[((bb * 64 + c) * 32 + hh) * 32 + ww], zo);
    }

    float d0 = r0 - ze0, d1 = r1 - ze1;
    float s = d0 * d0 + d1 * d1;
#pragma unroll
    for (int off = 16; off; off >>= 1) s += __shfl_xor_sync(0xFFFFFFFFu, s, off);
    if (lane == 0) bsum[warp] = s;
    __syncthreads();
    if (threadIdx.x == 0) {
        float t = bsum[0] + bsum[1] + bsum[2] + bsum[3];
        atomicAdd(out + LOSS_OFF, t * (1.25f / (float)ZELEMS));
    }

    if (lane == 0) {
        float* co = out + COEF_OFF;
        __stcs(&co[(size_t)I[0] * NB + j], x[0]);
        __stcs(&co[(size_t)I[1] * NB + j], x[1]);
        __stcs(&co[(size_t)I[2] * NB + j], x[2]);
        __stcs(&co[(size_t)I[3] * NB + j], x[3]);
        __stcs(&co[(size_t)I[4] * NB + j], x[4]);
    }
}

// ---------------------------------------------------------------------------
extern "C" void kernel_launch(void* const* d_in, const int* in_sizes, int n_in,
                              void* d_out, int out_size) {
    const float* ze = (const float*)d_in[0];  // (32, 64, 32, 32)
    const float* D = (const float*)d_in[1];   // (64, 512)
    float* out = (float*)d_out;

    cudaFuncSetAttribute(k_gemm_mma,
                         cudaFuncAttributeMaxDynamicSharedMemorySize, 98304);

    int ztail = out_size - LOSS_OFF;  // loss + coefficients
    k_prep<<<4096, 256>>>(out, ztail, D);
    k_ssplit<<<1024, 256>>>(ze);
    k_gemm_mma<<<dim3(NB / 128, NA / 128), 256, 98304>>>();
    k_omp<<<NB / 4, 128>>>(out);
}

// round 8
// speedup vs baseline: 1.3781x; 1.0376x over previous
#include <cuda_runtime.h>
#include <cuda_bf16.h>
#include <cstdint>

// Problem constants
#define NB 32768   // number of signals (B)
#define NA 512     // number of atoms (N)
#define MD 64      // embedding dim (M)
#define SP 5       // sparsity
#define ZELEMS 2097152        // 32*64*32*32
#define LOSS_OFF ZELEMS       // loss scalar offset in d_out
#define COEF_OFF (ZELEMS + 1) // coefficients offset in d_out

// Scratch (static __device__ — no allocation allowed)
__device__ float g_Zt[NB * MD];   // Z transposed: [j][m], 8 MB
__device__ float g_H[NB * NA];    // h_bar: [j][n], 64 MB (keep L2-warm)
__device__ float g_G[NA * NA];    // Gram D^T D, 1 MB
__device__ float g_Dt[NA * MD];   // D transposed: [n][m], 128 KB
// bf16 3-way-split operands, pre-swizzled rows of 128 B
__device__ __align__(16) __nv_bfloat16 g_A[3][NB * MD];
__device__ __align__(16) __nv_bfloat16 g_B[3][NA * MD];

__host__ __device__ __forceinline__ uint32_t sw128(uint32_t o) {
    return o ^ ((o >> 3) & 0x70);
}
__device__ __forceinline__ uint32_t smem_u32(const void* p) {
    uint32_t a;
    asm("{ .reg .u64 t; cvta.to.shared.u64 t, %1; cvt.u32.u64 %0, t; }"
        : "=r"(a) : "l"(p));
    return a;
}
__device__ __forceinline__ uint32_t swaddr(uint32_t base, int row, int colbyte) {
    uint32_t o = (uint32_t)(row * 128 + colbyte);
    return base + (o ^ ((uint32_t)(row & 7) << 4));
}

// ---------------------------------------------------------------------------
// k_prep: zero loss+coef (streaming stores), Dt transpose + B split,
// and (blocks < 256) the Gram matrix tiles.
// ---------------------------------------------------------------------------
__global__ void k_prep(float* __restrict__ out, int nfloats,
                       const float* __restrict__ D) {
    __shared__ float Da[32 * 65];
    __shared__ float Db[32 * 65];
    int tid = blockIdx.x * blockDim.x + threadIdx.x;

    float4* p = (float4*)(out + LOSS_OFF);
    int n4 = nfloats >> 2;
    float4 z4 = make_float4(0.f, 0.f, 0.f, 0.f);
    for (int i = tid; i < n4; i += gridDim.x * blockDim.x) __stcs(p + i, z4);
    if (blockIdx.x == 0 && threadIdx.x < (nfloats & 3))
        out[LOSS_OFF + (n4 << 2) + threadIdx.x] = 0.f;

    if (tid < MD * NA) {
        int m = tid >> 9;
        int n = tid & (NA - 1);
        float v = D[tid];
        g_Dt[n * MD + m] = v;
        __nv_bfloat16 bh = __float2bfloat16(v);
        float r1 = v - __bfloat162float(bh);
        __nv_bfloat16 bm = __float2bfloat16(r1);
        float r2 = r1 - __bfloat162float(bm);
        __nv_bfloat16 bl = __float2bfloat16(r2);
        uint32_t so = sw128((uint32_t)(n * 128 + m * 2));
        *(__nv_bfloat16*)((char*)g_B[0] + so) = bh;
        *(__nv_bfloat16*)((char*)g_B[1] + so) = bm;
        *(__nv_bfloat16*)((char*)g_B[2] + so) = bl;
    }

    // Gram tiles on blocks [0, 256)
    if (blockIdx.x < 256) {
        int a0 = (blockIdx.x >> 4) * 32, b0 = (blockIdx.x & 15) * 32;
        int t = threadIdx.x;  // 256
#pragma unroll
        for (int it = 0; it < 8; it++) {
            int e = t + it * 256;
            int aa = e & 31, m = e >> 5;
            Da[aa * 65 + m] = D[m * NA + a0 + aa];
            Db[aa * 65 + m] = D[m * NA + b0 + aa];
        }
        __syncthreads();
        int tb = t & 15, ta = t >> 4;
        float acc[2][2] = {};
#pragma unroll
        for (int m = 0; m < MD; m++) {
            float a0v = Da[(2 * ta) * 65 + m];
            float a1v = Da[(2 * ta + 1) * 65 + m];
            float b0v = Db[(2 * tb) * 65 + m];
            float b1v = Db[(2 * tb + 1) * 65 + m];
            acc[0][0] += a0v * b0v; acc[0][1] += a0v * b1v;
            acc[1][0] += a1v * b0v; acc[1][1] += a1v * b1v;
        }
#pragma unroll
        for (int i = 0; i < 2; i++)
#pragma unroll
            for (int l = 0; l < 2; l++)
                g_G[(a0 + 2 * ta + i) * NA + (b0 + 2 * tb + l)] = acc[i][l];
    }
}

// ---------------------------------------------------------------------------
// Fused scatter + bf16 split.
// Inverse map: for f = m*32768+j,  g = (m>>1)<<16 | (j&63)<<10 | (m&1)<<9
//                                      | ((j>>11)&15)<<5 | ((j>>6)&31)
// ---------------------------------------------------------------------------
__global__ void k_ssplit(const float* __restrict__ ze) {
    int t = blockIdx.x * blockDim.x + threadIdx.x;  // 262144
    int lane = t & 31;
    int grp = (t >> 5) & 7;         // m-group of 8
    int jlow6 = (t >> 8) & 63;      // c
    int jhi4 = t >> 14;             // j>>11
    int j = (jhi4 << 11) | (lane << 6) | jlow6;

    int base_g = ((grp * 4) << 16) | (jlow6 << 10) | (jhi4 << 5) | lane;
    float v[8];
#pragma unroll
    for (int e = 0; e < 8; e++)
        v[e] = __ldcs(ze + base_g + ((e >> 1) << 16) + ((e & 1) << 9));

    float4* zt4 = (float4*)(g_Zt + j * MD + grp * 8);
    zt4[0] = make_float4(v[0], v[1], v[2], v[3]);
    zt4[1] = make_float4(v[4], v[5], v[6], v[7]);

    unsigned short hs[8], ms[8], ls[8];
#pragma unroll
    for (int i = 0; i < 8; i++) {
        __nv_bfloat16 bh = __float2bfloat16(v[i]);
        float r1 = v[i] - __bfloat162float(bh);
        __nv_bfloat16 bm = __float2bfloat16(r1);
        float r2 = r1 - __bfloat162float(bm);
        __nv_bfloat16 bl = __float2bfloat16(r2);
        hs[i] = __bfloat16_as_ushort(bh);
        ms[i] = __bfloat16_as_ushort(bm);
        ls[i] = __bfloat16_as_ushort(bl);
    }
    int tile = j >> 7, r = j & 127;
    uint32_t so = sw128((uint32_t)(r * 128 + grp * 16));
    size_t off = (size_t)tile * 16384 + so;
    *(uint4*)((char*)g_A[0] + off) =
        make_uint4(hs[0] | (hs[1] << 16), hs[2] | (hs[3] << 16),
                   hs[4] | (hs[5] << 16), hs[6] | (hs[7] << 16));
    *(uint4*)((char*)g_A[1] + off) =
        make_uint4(ms[0] | (ms[1] << 16), ms[2] | (ms[3] << 16),
                   ms[4] | (ms[5] << 16), ms[6] | (ms[7] << 16));
    *(uint4*)((char*)g_A[2] + off) =
        make_uint4(ls[0] | (ls[1] << 16), ls[2] | (ls[3] << 16),
                   ls[4] | (ls[5] << 16), ls[6] | (ls[7] << 16));
}

// ---------------------------------------------------------------------------
// HMMA GEMM, 3-way bf16 split, gray-code product order.
// ---------------------------------------------------------------------------
__global__ __launch_bounds__(256, 2) void k_gemm_mma() {
    extern __shared__ char smem[];
    uint32_t sb = smem_u32(smem);
    int tid = threadIdx.x;
    int wid = tid >> 5, lane = tid & 31;
    int j0 = blockIdx.x * 128;
    int n0 = blockIdx.y * 128;

#pragma unroll
    for (int p = 0; p < 3; p++) {
        const uint4* srcA = (const uint4*)g_A[p] + blockIdx.x * 1024;
        uint4* dstA = (uint4*)(smem + p * 16384);
        const uint4* srcB = (const uint4*)g_B[p] + blockIdx.y * 1024;
        uint4* dstB = (uint4*)(smem + 49152 + p * 16384);
#pragma unroll
        for (int it = 0; it < 4; it++) {
            dstA[tid + it * 256] = srcA[tid + it * 256];
            dstB[tid + it * 256] = srcB[tid + it * 256];
        }
    }
    __syncthreads();

    int warpm = wid & 3, warpn = wid >> 2;
    float acc[2][8][4] = {};

    const int GA[6] = {0, 0, 1, 1, 0, 2};
    const int GB[6] = {2, 1, 1, 0, 0, 0};

#pragma unroll
    for (int k = 0; k < 64; k += 16) {
        uint32_t a[2][4];
        uint32_t b[8][2];
#pragma unroll
        for (int s = 0; s < 6; s++) {
            if (s == 0 || GA[s] != GA[s - 1]) {
                uint32_t aBase = sb + GA[s] * 16384;
#pragma unroll
                for (int mt = 0; mt < 2; mt++) {
                    int arow = warpm * 32 + mt * 16 + (lane & 15);
                    int acol = k + ((lane >> 4) << 3);
                    uint32_t addr = swaddr(aBase, arow, acol * 2);
                    asm volatile(
                        "ldmatrix.sync.aligned.m8n8.x4.shared.b16 {%0,%1,%2,%3}, [%4];"
                        : "=r"(a[mt][0]), "=r"(a[mt][1]), "=r"(a[mt][2]),
                          "=r"(a[mt][3])
                        : "r"(addr));
                }
            }
            if (s == 0 || GB[s] != GB[s - 1]) {
                uint32_t bBase = sb + 49152 + GB[s] * 16384;
#pragma unroll
                for (int np = 0; np < 4; np++) {
                    int brow = warpn * 64 + np * 16 + ((lane >> 4) << 3) + (lane & 7);
                    int bcol = k + (((lane >> 3) & 1) << 3);
                    uint32_t addr = swaddr(bBase, brow, bcol * 2);
                    uint32_t r0, r1, r2, r3;
                    asm volatile(
                        "ldmatrix.sync.aligned.m8n8.x4.shared.b16 {%0,%1,%2,%3}, [%4];"
                        : "=r"(r0), "=r"(r1), "=r"(r2), "=r"(r3) : "r"(addr));
                    b[np * 2][0] = r0;     b[np * 2][1] = r1;
                    b[np * 2 + 1][0] = r2; b[np * 2 + 1][1] = r3;
                }
            }
#pragma unroll
            for (int mt = 0; mt < 2; mt++)
#pragma unroll
                for (int nt = 0; nt < 8; nt++) {
                    asm volatile(
                        "mma.sync.aligned.m16n8k16.row.col.f32.bf16.bf16.f32 "
                        "{%0,%1,%2,%3}, {%4,%5,%6,%7}, {%8,%9}, {%0,%1,%2,%3};"
                        : "+f"(acc[mt][nt][0]), "+f"(acc[mt][nt][1]),
                          "+f"(acc[mt][nt][2]), "+f"(acc[mt][nt][3])
                        : "r"(a[mt][0]), "r"(a[mt][1]), "r"(a[mt][2]),
                          "r"(a[mt][3]), "r"(b[nt][0]), "r"(b[nt][1]));
                }
        }
    }

    int rbase = j0 + warpm * 32 + (lane >> 2);
    int cbase = n0 + warpn * 64 + (lane & 3) * 2;
#pragma unroll
    for (int mt = 0; mt < 2; mt++)
#pragma unroll
        for (int nt = 0; nt < 8; nt++) {
            int r = rbase + mt * 16;
            int c = cbase + nt * 8;
            *(float2*)&g_H[(size_t)r * NA + c] =
                make_float2(acc[mt][nt][0], acc[mt][nt][1]);
            *(float2*)&g_H[(size_t)(r + 8) * NA + c] =
                make_float2(acc[mt][nt][2], acc[mt][nt][3]);
        }
}

// ---------------------------------------------------------------------------
// OMP, incremental-residual formulation.
//   C = G[:,I] L^-T ;  h = hbar - C y ;  y append-only.
//   c_k = (G[n_k] - sum_{j<k} L_kj c_j) * rinv_k  (c_1..c_4 in smem, c_5 unused)
//   hbar[n_k] = h_sel + sum_{j<k} y_j c_j[n_k]
//   gv_i = G[n_i][n_k] = sum_{j<=i} L_ij c_j[n_k]
// Selected atoms are force-zeroed in h => no mask checks in the argmax.
// ---------------------------------------------------------------------------
__global__ __launch_bounds__(128, 6) void k_omp(float* __restrict__ out) {
    __shared__ float sC[4][4 * NA];  // c_1..c_4 per warp: 32 KB
    __shared__ float bsum[4];
    int warp = threadIdx.x >> 5;
    int lane = threadIdx.x & 31;
    int j = blockIdx.x * 4 + warp;
    float* cw = sC[warp];
    float4* cw4 = (float4*)cw;

    // h = hbar initially; n = lane*4 + 128*q + e
    float4 h4[4];
    const float4* hrow4 = (const float4*)(g_H + (size_t)j * NA);
#pragma unroll
    for (int q = 0; q < 4; q++) h4[q] = hrow4[lane + 32 * q];

    float L[SP][SP];
    float rinv[SP];
    float y[SP];
    float x[SP];
    int I[SP];
    unsigned mask16 = 0;

#pragma unroll
    for (int k = 1; k <= SP; k++) {
        // ---- argmax over |h| (masked entries are exactly 0) ----
        float bestu = -1.0f;
        int bestn = 0;
        float bhv = 0.0f;
#pragma unroll
        for (int q = 0; q < 4; q++) {
            float hv[4] = {h4[q].x, h4[q].y, h4[q].z, h4[q].w};
#pragma unroll
            for (int e = 0; e < 4; e++) {
                float u = fabsf(hv[e]);
                if (u > bestu) {
                    bestu = u;
                    bestn = lane * 4 + 128 * q + e;
                    bhv = hv[e];
                }
            }
        }
#pragma unroll
        for (int off = 16; off; off >>= 1) {
            float ou = __shfl_xor_sync(0xFFFFFFFFu, bestu, off);
            int on = __shfl_xor_sync(0xFFFFFFFFu, bestn, off);
            float ob = __shfl_xor_sync(0xFFFFFFFFu, bhv, off);
            if (ou > bestu || (ou == bestu && on < bestn)) {
                bestu = ou; bestn = on; bhv = ob;
            }
        }
        I[k - 1] = bestn;

        // ---- broadcasts of c_j[bestn] ----
        float cb[4];
#pragma unroll
        for (int jj = 0; jj < 4; jj++)
            if (jj < k - 1) cb[jj] = cw[jj * NA + bestn];

        // ---- hbar[bestn] reconstruction ----
        float hbk = bhv;
#pragma unroll
        for (int jj = 0; jj < 4; jj++)
            if (jj < k - 1) hbk += y[jj] * cb[jj];

        // ---- L row k (division-free) ----
        if (k == 1) {
            L[0][0] = 1.0f;
            rinv[0] = 1.0f;
        } else {
            float w[SP - 1];
            float ss = 0.0f;
#pragma unroll
            for (int i = 0; i < SP - 1; i++) {
                if (i < k - 1) {
                    float gvi = 0.0f;
#pragma unroll
                    for (int jj = 0; jj < SP - 1; jj++)
                        if (jj <= i) gvi += L[i][jj] * cb[jj];
                    float s = gvi;
#pragma unroll
                    for (int j2 = 0; j2 < SP - 1; j2++)
                        if (j2 < i) s -= L[i][j2] * w[j2];
                    w[i] = s * rinv[i];
                    ss += w[i] * w[i];
                }
            }
#pragma unroll
            for (int j2 = 0; j2 < SP - 1; j2++)
                if (j2 < k - 1) L[k - 1][j2] = w[j2];
            float v = fmaxf(1.0f - ss, 0.0f);
            float rs = rsqrtf(v);
            L[k - 1][k - 1] = v * rs;
            rinv[k - 1] = rs;
        }

        // ---- y_k (append-only forward substitution) ----
        {
            float s = hbk;
#pragma unroll
            for (int j2 = 0; j2 < SP - 1; j2++)
                if (j2 < k - 1) s -= L[k - 1][j2] * y[j2];
            y[k - 1] = s * rinv[k - 1];
        }

        // ---- mask the new atom ----
        if (((bestn >> 2) & 31) == lane)
            mask16 |= 1u << (((bestn >> 7) << 2) | (bestn & 3));

        // ---- c_k + h update (skipped for the last iteration) ----
        if (k < SP) {
            const float4* grow4 = (const float4*)(g_G + (size_t)bestn * NA);
            float yk = y[k - 1];
            float rk = rinv[k - 1];
#pragma unroll
            for (int q = 0; q < 4; q++) {
                float4 g4 = grow4[lane + 32 * q];
                float4 c4 = g4;
#pragma unroll
                for (int jj = 0; jj < 3; jj++) {
                    if (jj < k - 1) {
                        float lkj = L[k - 1][jj];
                        float4 cj = cw4[jj * 128 + lane + 32 * q];
                        c4.x -= lkj * cj.x; c4.y -= lkj * cj.y;
                        c4.z -= lkj * cj.z; c4.w -= lkj * cj.w;
                    }
                }
                c4.x *= rk; c4.y *= rk; c4.z *= rk; c4.w *= rk;
                cw4[(k - 1) * 128 + lane + 32 * q] = c4;
                float4 hh = h4[q];
                hh.x -= yk * c4.x; hh.y -= yk * c4.y;
                hh.z -= yk * c4.z; hh.w -= yk * c4.w;
                // force-zero all selected atoms owned by this lane
                if ((mask16 >> (q * 4 + 0)) & 1u) hh.x = 0.0f;
                if ((mask16 >> (q * 4 + 1)) & 1u) hh.y = 0.0f;
                if ((mask16 >> (q * 4 + 2)) & 1u) hh.z = 0.0f;
                if ((mask16 >> (q * 4 + 3)) & 1u) hh.w = 0.0f;
                h4[q] = hh;
            }
            __syncwarp();
        }
    }

    // ---- x = L^-T y (back substitution, division-free) ----
#pragma unroll
    for (int i = SP - 1; i >= 0; i--) {
        float s = y[i];
#pragma unroll
        for (int j2 = i + 1; j2 < SP; j2++) s -= L[j2][i] * x[j2];
        x[i] = s * rinv[i];
    }

    // ---- reconstruction + outputs ----
    float ze0 = g_Zt[j * MD + lane];
    float ze1 = g_Zt[j * MD + 32 + lane];
    float r0 = 0.f, r1 = 0.f;
#pragma unroll
    for (int i = 0; i < SP; i++) {
        const float* dcol = g_Dt + I[i] * MD;
        r0 += x[i] * dcol[lane];
        r1 += x[i] * dcol[32 + lane];
    }

    // z_out scattered back to NCHW: c=f&63, w=(f>>6)&31, h=(f>>11)&31, b=f>>16
#pragma unroll
    for (int p = 0; p < 2; p++) {
        int m = lane + 32 * p;
        float rm = p ? r1 : r0;
        float ze = p ? ze1 : ze0;
        float zo = ze + (rm - ze);
        int f = (m << 15) | j;
        int c = f & 63, ww = (f >> 6) & 31, hh = (f >> 11) & 31, bb = f >> 16;
        __stcs(&out[((bb * 64 + c) * 32 + hh) * 32 + ww], zo);
    }

    float d0 = r0 - ze0, d1 = r1 - ze1;
    float s = d0 * d0 + d1 * d1;
#pragma unroll
    for (int off = 16; off; off >>= 1) s += __shfl_xor_sync(0xFFFFFFFFu, s, off);
    if (lane == 0) bsum[warp] = s;
    __syncthreads();
    if (threadIdx.x == 0) {
        float t = bsum[0] + bsum[1] + bsum[2] + bsum[3];
        atomicAdd(out + LOSS_OFF, t * (1.25f / (float)ZELEMS));
    }

    if (lane == 0) {
        float* co = out + COEF_OFF;
        __stcs(&co[(size_t)I[0] * NB + j], x[0]);
        __stcs(&co[(size_t)I[1] * NB + j], x[1]);
        __stcs(&co[(size_t)I[2] * NB + j], x[2]);
        __stcs(&co[(size_t)I[3] * NB + j], x[3]);
        __stcs(&co[(size_t)I[4] * NB + j], x[4]);
    }
}

// ---------------------------------------------------------------------------
extern "C" void kernel_launch(void* const* d_in, const int* in_sizes, int n_in,
                              void* d_out, int out_size) {
    const float* ze = (const float*)d_in[0];  // (32, 64, 32, 32)
    const float* D = (const float*)d_in[1];   // (64, 512)
    float* out = (float*)d_out;

    cudaFuncSetAttribute(k_gemm_mma,
                         cudaFuncAttributeMaxDynamicSharedMemorySize, 98304);

    int ztail = out_size - LOSS_OFF;  // loss + coefficients
    k_prep<<<4096, 256>>>(out, ztail, D);
    k_ssplit<<<1024, 256>>>(ze);
    k_gemm_mma<<<dim3(NB / 128, NA / 128), 256, 98304>>>();
    k_omp<<<NB / 4, 128>>>(out);
}

// round 9
// speedup vs baseline: 1.5203x; 1.1032x over previous
#include <cuda_runtime.h>
#include <cuda_bf16.h>
#include <cstdint>

// Problem constants
#define NB 32768   // number of signals (B)
#define NA 512     // number of atoms (N)
#define MD 64      // embedding dim (M)
#define SP 5       // sparsity
#define ZELEMS 2097152        // 32*64*32*32
#define LOSS_OFF ZELEMS       // loss scalar offset in d_out
#define COEF_OFF (ZELEMS + 1) // coefficients offset in d_out

// Scratch (static __device__ — no allocation allowed)
__device__ float g_Zt[NB * MD];   // Z transposed: [j][m], 8 MB
__device__ float g_H[NB * NA];    // h_bar: [j][n], 64 MB (keep L2-warm)
__device__ float g_G[NA * NA];    // Gram D^T D, 1 MB
__device__ float g_Dt[NA * MD];   // D transposed: [n][m], 128 KB
// bf16 3-way-split operands, pre-swizzled rows of 128 B
__device__ __align__(16) __nv_bfloat16 g_A[3][NB * MD];
__device__ __align__(16) __nv_bfloat16 g_B[3][NA * MD];

__host__ __device__ __forceinline__ uint32_t sw128(uint32_t o) {
    return o ^ ((o >> 3) & 0x70);
}
__device__ __forceinline__ uint32_t smem_u32(const void* p) {
    uint32_t a;
    asm("{ .reg .u64 t; cvta.to.shared.u64 t, %1; cvt.u32.u64 %0, t; }"
        : "=r"(a) : "l"(p));
    return a;
}
__device__ __forceinline__ uint32_t swaddr(uint32_t base, int row, int colbyte) {
    uint32_t o = (uint32_t)(row * 128 + colbyte);
    return base + (o ^ ((uint32_t)(row & 7) << 4));
}

// ---------------------------------------------------------------------------
// k_prep: zero loss+coef (streaming stores), Dt transpose + B split,
// and (blocks < 256) the Gram matrix tiles.
// ---------------------------------------------------------------------------
__global__ void k_prep(float* __restrict__ out, int nfloats,
                       const float* __restrict__ D) {
    __shared__ float Da[32 * 65];
    __shared__ float Db[32 * 65];
    int tid = blockIdx.x * blockDim.x + threadIdx.x;

    float4* p = (float4*)(out + LOSS_OFF);
    int n4 = nfloats >> 2;
    float4 z4 = make_float4(0.f, 0.f, 0.f, 0.f);
    for (int i = tid; i < n4; i += gridDim.x * blockDim.x) __stcs(p + i, z4);
    if (blockIdx.x == 0 && threadIdx.x < (nfloats & 3))
        out[LOSS_OFF + (n4 << 2) + threadIdx.x] = 0.f;

    if (tid < MD * NA) {
        int m = tid >> 9;
        int n = tid & (NA - 1);
        float v = D[tid];
        g_Dt[n * MD + m] = v;
        __nv_bfloat16 bh = __float2bfloat16(v);
        float r1 = v - __bfloat162float(bh);
        __nv_bfloat16 bm = __float2bfloat16(r1);
        float r2 = r1 - __bfloat162float(bm);
        __nv_bfloat16 bl = __float2bfloat16(r2);
        uint32_t so = sw128((uint32_t)(n * 128 + m * 2));
        *(__nv_bfloat16*)((char*)g_B[0] + so) = bh;
        *(__nv_bfloat16*)((char*)g_B[1] + so) = bm;
        *(__nv_bfloat16*)((char*)g_B[2] + so) = bl;
    }

    // Gram tiles on blocks [0, 256)
    if (blockIdx.x < 256) {
        int a0 = (blockIdx.x >> 4) * 32, b0 = (blockIdx.x & 15) * 32;
        int t = threadIdx.x;  // 256
#pragma unroll
        for (int it = 0; it < 8; it++) {
            int e = t + it * 256;
            int aa = e & 31, m = e >> 5;
            Da[aa * 65 + m] = D[m * NA + a0 + aa];
            Db[aa * 65 + m] = D[m * NA + b0 + aa];
        }
        __syncthreads();
        int tb = t & 15, ta = t >> 4;
        float acc[2][2] = {};
#pragma unroll
        for (int m = 0; m < MD; m++) {
            float a0v = Da[(2 * ta) * 65 + m];
            float a1v = Da[(2 * ta + 1) * 65 + m];
            float b0v = Db[(2 * tb) * 65 + m];
            float b1v = Db[(2 * tb + 1) * 65 + m];
            acc[0][0] += a0v * b0v; acc[0][1] += a0v * b1v;
            acc[1][0] += a1v * b0v; acc[1][1] += a1v * b1v;
        }
#pragma unroll
        for (int i = 0; i < 2; i++)
#pragma unroll
            for (int l = 0; l < 2; l++)
                g_G[(a0 + 2 * ta + i) * NA + (b0 + 2 * tb + l)] = acc[i][l];
    }
}

// ---------------------------------------------------------------------------
// Fused scatter + bf16 split.
// Inverse map: for f = m*32768+j,  g = (m>>1)<<16 | (j&63)<<10 | (m&1)<<9
//                                      | ((j>>11)&15)<<5 | ((j>>6)&31)
// ---------------------------------------------------------------------------
__global__ void k_ssplit(const float* __restrict__ ze) {
    int t = blockIdx.x * blockDim.x + threadIdx.x;  // 262144
    int lane = t & 31;
    int grp = (t >> 5) & 7;         // m-group of 8
    int jlow6 = (t >> 8) & 63;      // c
    int jhi4 = t >> 14;             // j>>11
    int j = (jhi4 << 11) | (lane << 6) | jlow6;

    int base_g = ((grp * 4) << 16) | (jlow6 << 10) | (jhi4 << 5) | lane;
    float v[8];
#pragma unroll
    for (int e = 0; e < 8; e++)
        v[e] = __ldcs(ze + base_g + ((e >> 1) << 16) + ((e & 1) << 9));

    float4* zt4 = (float4*)(g_Zt + j * MD + grp * 8);
    zt4[0] = make_float4(v[0], v[1], v[2], v[3]);
    zt4[1] = make_float4(v[4], v[5], v[6], v[7]);

    unsigned short hs[8], ms[8], ls[8];
#pragma unroll
    for (int i = 0; i < 8; i++) {
        __nv_bfloat16 bh = __float2bfloat16(v[i]);
        float r1 = v[i] - __bfloat162float(bh);
        __nv_bfloat16 bm = __float2bfloat16(r1);
        float r2 = r1 - __bfloat162float(bm);
        __nv_bfloat16 bl = __float2bfloat16(r2);
        hs[i] = __bfloat16_as_ushort(bh);
        ms[i] = __bfloat16_as_ushort(bm);
        ls[i] = __bfloat16_as_ushort(bl);
    }
    int tile = j >> 7, r = j & 127;
    uint32_t so = sw128((uint32_t)(r * 128 + grp * 16));
    size_t off = (size_t)tile * 16384 + so;
    *(uint4*)((char*)g_A[0] + off) =
        make_uint4(hs[0] | (hs[1] << 16), hs[2] | (hs[3] << 16),
                   hs[4] | (hs[5] << 16), hs[6] | (hs[7] << 16));
    *(uint4*)((char*)g_A[1] + off) =
        make_uint4(ms[0] | (ms[1] << 16), ms[2] | (ms[3] << 16),
                   ms[4] | (ms[5] << 16), ms[6] | (ms[7] << 16));
    *(uint4*)((char*)g_A[2] + off) =
        make_uint4(ls[0] | (ls[1] << 16), ls[2] | (ls[3] << 16),
                   ls[4] | (ls[5] << 16), ls[6] | (ls[7] << 16));
}

// ---------------------------------------------------------------------------
// HMMA GEMM, 3-way bf16 split, gray-code product order.
// ---------------------------------------------------------------------------
__global__ __launch_bounds__(256, 2) void k_gemm_mma() {
    extern __shared__ char smem[];
    uint32_t sb = smem_u32(smem);
    int tid = threadIdx.x;
    int wid = tid >> 5, lane = tid & 31;
    int j0 = blockIdx.x * 128;
    int n0 = blockIdx.y * 128;

#pragma unroll
    for (int p = 0; p < 3; p++) {
        const uint4* srcA = (const uint4*)g_A[p] + blockIdx.x * 1024;
        uint4* dstA = (uint4*)(smem + p * 16384);
        const uint4* srcB = (const uint4*)g_B[p] + blockIdx.y * 1024;
        uint4* dstB = (uint4*)(smem + 49152 + p * 16384);
#pragma unroll
        for (int it = 0; it < 4; it++) {
            dstA[tid + it * 256] = srcA[tid + it * 256];
            dstB[tid + it * 256] = srcB[tid + it * 256];
        }
    }
    __syncthreads();

    int warpm = wid & 3, warpn = wid >> 2;
    float acc[2][8][4] = {};

    const int GA[6] = {0, 0, 1, 1, 0, 2};
    const int GB[6] = {2, 1, 1, 0, 0, 0};

#pragma unroll
    for (int k = 0; k < 64; k += 16) {
        uint32_t a[2][4];
        uint32_t b[8][2];
#pragma unroll
        for (int s = 0; s < 6; s++) {
            if (s == 0 || GA[s] != GA[s - 1]) {
                uint32_t aBase = sb + GA[s] * 16384;
#pragma unroll
                for (int mt = 0; mt < 2; mt++) {
                    int arow = warpm * 32 + mt * 16 + (lane & 15);
                    int acol = k + ((lane >> 4) << 3);
                    uint32_t addr = swaddr(aBase, arow, acol * 2);
                    asm volatile(
                        "ldmatrix.sync.aligned.m8n8.x4.shared.b16 {%0,%1,%2,%3}, [%4];"
                        : "=r"(a[mt][0]), "=r"(a[mt][1]), "=r"(a[mt][2]),
                          "=r"(a[mt][3])
                        : "r"(addr));
                }
            }
            if (s == 0 || GB[s] != GB[s - 1]) {
                uint32_t bBase = sb + 49152 + GB[s] * 16384;
#pragma unroll
                for (int np = 0; np < 4; np++) {
                    int brow = warpn * 64 + np * 16 + ((lane >> 4) << 3) + (lane & 7);
                    int bcol = k + (((lane >> 3) & 1) << 3);
                    uint32_t addr = swaddr(bBase, brow, bcol * 2);
                    uint32_t r0, r1, r2, r3;
                    asm volatile(
                        "ldmatrix.sync.aligned.m8n8.x4.shared.b16 {%0,%1,%2,%3}, [%4];"
                        : "=r"(r0), "=r"(r1), "=r"(r2), "=r"(r3) : "r"(addr));
                    b[np * 2][0] = r0;     b[np * 2][1] = r1;
                    b[np * 2 + 1][0] = r2; b[np * 2 + 1][1] = r3;
                }
            }
#pragma unroll
            for (int mt = 0; mt < 2; mt++)
#pragma unroll
                for (int nt = 0; nt < 8; nt++) {
                    asm volatile(
                        "mma.sync.aligned.m16n8k16.row.col.f32.bf16.bf16.f32 "
                        "{%0,%1,%2,%3}, {%4,%5,%6,%7}, {%8,%9}, {%0,%1,%2,%3};"
                        : "+f"(acc[mt][nt][0]), "+f"(acc[mt][nt][1]),
                          "+f"(acc[mt][nt][2]), "+f"(acc[mt][nt][3])
                        : "r"(a[mt][0]), "r"(a[mt][1]), "r"(a[mt][2]),
                          "r"(a[mt][3]), "r"(b[nt][0]), "r"(b[nt][1]));
                }
        }
    }

    int rbase = j0 + warpm * 32 + (lane >> 2);
    int cbase = n0 + warpn * 64 + (lane & 3) * 2;
#pragma unroll
    for (int mt = 0; mt < 2; mt++)
#pragma unroll
        for (int nt = 0; nt < 8; nt++) {
            int r = rbase + mt * 16;
            int c = cbase + nt * 8;
            *(float2*)&g_H[(size_t)r * NA + c] =
                make_float2(acc[mt][nt][0], acc[mt][nt][1]);
            *(float2*)&g_H[(size_t)(r + 8) * NA + c] =
                make_float2(acc[mt][nt][2], acc[mt][nt][3]);
        }
}

// ---------------------------------------------------------------------------
// OMP, incremental-residual + cheap argmax:
//   - value-only max via FMNMX (fused into the h-update loop for iters 2..5)
//   - index via per-lane equality bitmask + __ffs + __reduce_min_sync
//     (bit = 4q+e is n-ascending within a lane -> exact first-max tie-break)
//   - hbar[bestn] reloaded from g_H (uniform LDG, exact reference value)
// ---------------------------------------------------------------------------
__global__ __launch_bounds__(128, 6) void k_omp(float* __restrict__ out) {
    __shared__ float sC[4][4 * NA];  // c_1..c_4 per warp: 32 KB
    __shared__ float bsum[4];
    int warp = threadIdx.x >> 5;
    int lane = threadIdx.x & 31;
    int j = blockIdx.x * 4 + warp;
    float* cw = sC[warp];
    float4* cw4 = (float4*)cw;

    const float* hrow = g_H + (size_t)j * NA;
    float4 h4[4];
    const float4* hrow4 = (const float4*)hrow;
#pragma unroll
    for (int q = 0; q < 4; q++) h4[q] = hrow4[lane + 32 * q];

    float L[SP][SP];
    float rinv[SP];
    float y[SP];
    float x[SP];
    int I[SP];
    unsigned mask16 = 0;

    // initial per-lane max of |h|
    float vmax = 0.0f;
#pragma unroll
    for (int q = 0; q < 4; q++) {
        vmax = fmaxf(vmax, fabsf(h4[q].x));
        vmax = fmaxf(vmax, fabsf(h4[q].y));
        vmax = fmaxf(vmax, fabsf(h4[q].z));
        vmax = fmaxf(vmax, fabsf(h4[q].w));
    }

#pragma unroll
    for (int k = 1; k <= SP; k++) {
        // ---- warp max ----
#pragma unroll
        for (int off = 16; off; off >>= 1)
            vmax = fmaxf(vmax, __shfl_xor_sync(0xFFFFFFFFu, vmax, off));

        // ---- equality bitmask (bit = 4q+e; n = 4*lane + 128q + e) ----
        unsigned eq = 0;
#pragma unroll
        for (int q = 0; q < 4; q++) {
            if (fabsf(h4[q].x) == vmax) eq |= 1u << (4 * q + 0);
            if (fabsf(h4[q].y) == vmax) eq |= 1u << (4 * q + 1);
            if (fabsf(h4[q].z) == vmax) eq |= 1u << (4 * q + 2);
            if (fabsf(h4[q].w) == vmax) eq |= 1u << (4 * q + 3);
        }
        int ncand = 0x7FFFFFFF;
        if (eq) {
            int b = __ffs(eq) - 1;
            ncand = (lane << 2) | ((b >> 2) << 7) | (b & 3);
        }
        int bestn = __reduce_min_sync(0xFFFFFFFFu, ncand);
        I[k - 1] = bestn;

        // ---- exact hbar[bestn] (uniform LDG; g_H row is unmodified) ----
        float hbk = __ldg(hrow + bestn);

        // ---- broadcasts of c_j[bestn] ----
        float cb[4];
#pragma unroll
        for (int jj = 0; jj < 4; jj++)
            if (jj < k - 1) cb[jj] = cw[jj * NA + bestn];

        // ---- L row k (division-free); gv_i = sum_{jj<=i} L_ij cb_jj ----
        if (k == 1) {
            L[0][0] = 1.0f;
            rinv[0] = 1.0f;
        } else {
            float w[SP - 1];
            float ss = 0.0f;
#pragma unroll
            for (int i = 0; i < SP - 1; i++) {
                if (i < k - 1) {
                    float gvi = 0.0f;
#pragma unroll
                    for (int jj = 0; jj < SP - 1; jj++)
                        if (jj <= i) gvi += L[i][jj] * cb[jj];
                    float s = gvi;
#pragma unroll
                    for (int j2 = 0; j2 < SP - 1; j2++)
                        if (j2 < i) s -= L[i][j2] * w[j2];
                    w[i] = s * rinv[i];
                    ss += w[i] * w[i];
                }
            }
#pragma unroll
            for (int j2 = 0; j2 < SP - 1; j2++)
                if (j2 < k - 1) L[k - 1][j2] = w[j2];
            float v = fmaxf(1.0f - ss, 0.0f);
            float rs = rsqrtf(v);
            L[k - 1][k - 1] = v * rs;
            rinv[k - 1] = rs;
        }

        // ---- y_k ----
        {
            float s = hbk;
#pragma unroll
            for (int j2 = 0; j2 < SP - 1; j2++)
                if (j2 < k - 1) s -= L[k - 1][j2] * y[j2];
            y[k - 1] = s * rinv[k - 1];
        }

        // ---- mask the new atom ----
        if (((bestn >> 2) & 31) == lane)
            mask16 |= 1u << (((bestn >> 7) << 2) | (bestn & 3));

        // ---- c_k + h update, fused next-max (skipped for last iteration) ----
        if (k < SP) {
            const float4* grow4 = (const float4*)(g_G + (size_t)bestn * NA);
            float yk = y[k - 1];
            float rk = rinv[k - 1];
            vmax = 0.0f;
#pragma unroll
            for (int q = 0; q < 4; q++) {
                float4 c4 = grow4[lane + 32 * q];
#pragma unroll
                for (int jj = 0; jj < 3; jj++) {
                    if (jj < k - 1) {
                        float lkj = L[k - 1][jj];
                        float4 cj = cw4[jj * 128 + lane + 32 * q];
                        c4.x -= lkj * cj.x; c4.y -= lkj * cj.y;
                        c4.z -= lkj * cj.z; c4.w -= lkj * cj.w;
                    }
                }
                c4.x *= rk; c4.y *= rk; c4.z *= rk; c4.w *= rk;
                cw4[(k - 1) * 128 + lane + 32 * q] = c4;
                float4 hh = h4[q];
                hh.x -= yk * c4.x; hh.y -= yk * c4.y;
                hh.z -= yk * c4.z; hh.w -= yk * c4.w;
                if ((mask16 >> (q * 4 + 0)) & 1u) hh.x = 0.0f;
                if ((mask16 >> (q * 4 + 1)) & 1u) hh.y = 0.0f;
                if ((mask16 >> (q * 4 + 2)) & 1u) hh.z = 0.0f;
                if ((mask16 >> (q * 4 + 3)) & 1u) hh.w = 0.0f;
                h4[q] = hh;
                vmax = fmaxf(vmax, fmaxf(fmaxf(fabsf(hh.x), fabsf(hh.y)),
                                         fmaxf(fabsf(hh.z), fabsf(hh.w))));
            }
            __syncwarp();
        }
    }

    // ---- x = L^-T y (back substitution, division-free) ----
#pragma unroll
    for (int i = SP - 1; i >= 0; i--) {
        float s = y[i];
#pragma unroll
        for (int j2 = i + 1; j2 < SP; j2++) s -= L[j2][i] * x[j2];
        x[i] = s * rinv[i];
    }

    // ---- reconstruction + outputs ----
    float ze0 = g_Zt[j * MD + lane];
    float ze1 = g_Zt[j * MD + 32 + lane];
    float r0 = 0.f, r1 = 0.f;
#pragma unroll
    for (int i = 0; i < SP; i++) {
        const float* dcol = g_Dt + I[i] * MD;
        r0 += x[i] * dcol[lane];
        r1 += x[i] * dcol[32 + lane];
    }

    // z_out scattered back to NCHW: c=f&63, w=(f>>6)&31, h=(f>>11)&31, b=f>>16
#pragma unroll
    for (int p = 0; p < 2; p++) {
        int m = lane + 32 * p;
        float rm = p ? r1 : r0;
        float ze = p ? ze1 : ze0;
        float zo = ze + (rm - ze);
        int f = (m << 15) | j;
        int c = f & 63, ww = (f >> 6) & 31, hh = (f >> 11) & 31, bb = f >> 16;
        __stcs(&out[((bb * 64 + c) * 32 + hh) * 32 + ww], zo);
    }

    float d0 = r0 - ze0, d1 = r1 - ze1;
    float s = d0 * d0 + d1 * d1;
#pragma unroll
    for (int off = 16; off; off >>= 1) s += __shfl_xor_sync(0xFFFFFFFFu, s, off);
    if (lane == 0) bsum[warp] = s;
    __syncthreads();
    if (threadIdx.x == 0) {
        float t = bsum[0] + bsum[1] + bsum[2] + bsum[3];
        atomicAdd(out + LOSS_OFF, t * (1.25f / (float)ZELEMS));
    }

    if (lane == 0) {
        float* co = out + COEF_OFF;
        __stcs(&co[(size_t)I[0] * NB + j], x[0]);
        __stcs(&co[(size_t)I[1] * NB + j], x[1]);
        __stcs(&co[(size_t)I[2] * NB + j], x[2]);
        __stcs(&co[(size_t)I[3] * NB + j], x[3]);
        __stcs(&co[(size_t)I[4] * NB + j], x[4]);
    }
}

// ---------------------------------------------------------------------------
extern "C" void kernel_launch(void* const* d_in, const int* in_sizes, int n_in,
                              void* d_out, int out_size) {
    const float* ze = (const float*)d_in[0];  // (32, 64, 32, 32)
    const float* D = (const float*)d_in[1];   // (64, 512)
    float* out = (float*)d_out;

    cudaFuncSetAttribute(k_gemm_mma,
                         cudaFuncAttributeMaxDynamicSharedMemorySize, 98304);

    int ztail = out_size - LOSS_OFF;  // loss + coefficients
    k_prep<<<4096, 256>>>(out, ztail, D);
    k_ssplit<<<1024, 256>>>(ze);
    k_gemm_mma<<<dim3(NB / 128, NA / 128), 256, 98304>>>();
    k_omp<<<NB / 4, 128>>>(out);
}

// round 10
// speedup vs baseline: 1.5586x; 1.0252x over previous
#include <cuda_runtime.h>
#include <cuda_bf16.h>
#include <cstdint>

// Problem constants
#define NB 32768   // number of signals (B)
#define NA 512     // number of atoms (N)
#define MD 64      // embedding dim (M)
#define SP 5       // sparsity
#define ZELEMS 2097152        // 32*64*32*32
#define LOSS_OFF ZELEMS       // loss scalar offset in d_out
#define COEF_OFF (ZELEMS + 1) // coefficients offset in d_out

// Scratch (static __device__ — no allocation allowed)
__device__ float g_Zt[NB * MD];   // Z transposed: [j][m], 8 MB
__device__ float g_H[NB * NA];    // h_bar: [j][n], 64 MB (keep L2-warm)
__device__ float g_G[NA * NA];    // Gram D^T D, 1 MB
__device__ float g_Dt[NA * MD];   // D transposed: [n][m], 128 KB
// bf16 3-way-split operands, pre-swizzled rows of 128 B
__device__ __align__(16) __nv_bfloat16 g_A[3][NB * MD];
__device__ __align__(16) __nv_bfloat16 g_B[3][NA * MD];

__host__ __device__ __forceinline__ uint32_t sw128(uint32_t o) {
    return o ^ ((o >> 3) & 0x70);
}
__device__ __forceinline__ uint32_t smem_u32(const void* p) {
    uint32_t a;
    asm("{ .reg .u64 t; cvta.to.shared.u64 t, %1; cvt.u32.u64 %0, t; }"
        : "=r"(a) : "l"(p));
    return a;
}
__device__ __forceinline__ uint32_t swaddr(uint32_t base, int row, int colbyte) {
    uint32_t o = (uint32_t)(row * 128 + colbyte);
    return base + (o ^ ((uint32_t)(row & 7) << 4));
}

// ---------------------------------------------------------------------------
// k_prep: zero loss+coef (streaming stores), Dt transpose + B split,
// and (blocks < 256) the Gram matrix tiles.
// ---------------------------------------------------------------------------
__global__ void k_prep(float* __restrict__ out, int nfloats,
                       const float* __restrict__ D) {
    __shared__ float Da[32 * 65];
    __shared__ float Db[32 * 65];
    int tid = blockIdx.x * blockDim.x + threadIdx.x;

    float4* p = (float4*)(out + LOSS_OFF);
    int n4 = nfloats >> 2;
    float4 z4 = make_float4(0.f, 0.f, 0.f, 0.f);
    for (int i = tid; i < n4; i += gridDim.x * blockDim.x) __stcs(p + i, z4);
    if (blockIdx.x == 0 && threadIdx.x < (nfloats & 3))
        out[LOSS_OFF + (n4 << 2) + threadIdx.x] = 0.f;

    if (tid < MD * NA) {
        int m = tid >> 9;
        int n = tid & (NA - 1);
        float v = D[tid];
        g_Dt[n * MD + m] = v;
        __nv_bfloat16 bh = __float2bfloat16(v);
        float r1 = v - __bfloat162float(bh);
        __nv_bfloat16 bm = __float2bfloat16(r1);
        float r2 = r1 - __bfloat162float(bm);
        __nv_bfloat16 bl = __float2bfloat16(r2);
        uint32_t so = sw128((uint32_t)(n * 128 + m * 2));
        *(__nv_bfloat16*)((char*)g_B[0] + so) = bh;
        *(__nv_bfloat16*)((char*)g_B[1] + so) = bm;
        *(__nv_bfloat16*)((char*)g_B[2] + so) = bl;
    }

    // Gram tiles on blocks [0, 256)
    if (blockIdx.x < 256) {
        int a0 = (blockIdx.x >> 4) * 32, b0 = (blockIdx.x & 15) * 32;
        int t = threadIdx.x;  // 256
#pragma unroll
        for (int it = 0; it < 8; it++) {
            int e = t + it * 256;
            int aa = e & 31, m = e >> 5;
            Da[aa * 65 + m] = D[m * NA + a0 + aa];
            Db[aa * 65 + m] = D[m * NA + b0 + aa];
        }
        __syncthreads();
        int tb = t & 15, ta = t >> 4;
        float acc[2][2] = {};
#pragma unroll
        for (int m = 0; m < MD; m++) {
            float a0v = Da[(2 * ta) * 65 + m];
            float a1v = Da[(2 * ta + 1) * 65 + m];
            float b0v = Db[(2 * tb) * 65 + m];
            float b1v = Db[(2 * tb + 1) * 65 + m];
            acc[0][0] += a0v * b0v; acc[0][1] += a0v * b1v;
            acc[1][0] += a1v * b0v; acc[1][1] += a1v * b1v;
        }
#pragma unroll
        for (int i = 0; i < 2; i++)
#pragma unroll
            for (int l = 0; l < 2; l++)
                g_G[(a0 + 2 * ta + i) * NA + (b0 + 2 * tb + l)] = acc[i][l];
    }
}

// ---------------------------------------------------------------------------
// Fused scatter + bf16 split.
// Inverse map: for f = m*32768+j,  g = (m>>1)<<16 | (j&63)<<10 | (m&1)<<9
//                                      | ((j>>11)&15)<<5 | ((j>>6)&31)
// ---------------------------------------------------------------------------
__global__ void k_ssplit(const float* __restrict__ ze) {
    int t = blockIdx.x * blockDim.x + threadIdx.x;  // 262144
    int lane = t & 31;
    int grp = (t >> 5) & 7;         // m-group of 8
    int jlow6 = (t >> 8) & 63;      // c
    int jhi4 = t >> 14;             // j>>11
    int j = (jhi4 << 11) | (lane << 6) | jlow6;

    int base_g = ((grp * 4) << 16) | (jlow6 << 10) | (jhi4 << 5) | lane;
    float v[8];
#pragma unroll
    for (int e = 0; e < 8; e++)
        v[e] = __ldcs(ze + base_g + ((e >> 1) << 16) + ((e & 1) << 9));

    float4* zt4 = (float4*)(g_Zt + j * MD + grp * 8);
    zt4[0] = make_float4(v[0], v[1], v[2], v[3]);
    zt4[1] = make_float4(v[4], v[5], v[6], v[7]);

    unsigned short hs[8], ms[8], ls[8];
#pragma unroll
    for (int i = 0; i < 8; i++) {
        __nv_bfloat16 bh = __float2bfloat16(v[i]);
        float r1 = v[i] - __bfloat162float(bh);
        __nv_bfloat16 bm = __float2bfloat16(r1);
        float r2 = r1 - __bfloat162float(bm);
        __nv_bfloat16 bl = __float2bfloat16(r2);
        hs[i] = __bfloat16_as_ushort(bh);
        ms[i] = __bfloat16_as_ushort(bm);
        ls[i] = __bfloat16_as_ushort(bl);
    }
    int tile = j >> 7, r = j & 127;
    uint32_t so = sw128((uint32_t)(r * 128 + grp * 16));
    size_t off = (size_t)tile * 16384 + so;
    *(uint4*)((char*)g_A[0] + off) =
        make_uint4(hs[0] | (hs[1] << 16), hs[2] | (hs[3] << 16),
                   hs[4] | (hs[5] << 16), hs[6] | (hs[7] << 16));
    *(uint4*)((char*)g_A[1] + off) =
        make_uint4(ms[0] | (ms[1] << 16), ms[2] | (ms[3] << 16),
                   ms[4] | (ms[5] << 16), ms[6] | (ms[7] << 16));
    *(uint4*)((char*)g_A[2] + off) =
        make_uint4(ls[0] | (ls[1] << 16), ls[2] | (ls[3] << 16),
                   ls[4] | (ls[5] << 16), ls[6] | (ls[7] << 16));
}

// ---------------------------------------------------------------------------
// HMMA GEMM, 3-way bf16 split, gray-code product order.
// ---------------------------------------------------------------------------
__global__ __launch_bounds__(256, 2) void k_gemm_mma() {
    extern __shared__ char smem[];
    uint32_t sb = smem_u32(smem);
    int tid = threadIdx.x;
    int wid = tid >> 5, lane = tid & 31;
    int j0 = blockIdx.x * 128;
    int n0 = blockIdx.y * 128;

#pragma unroll
    for (int p = 0; p < 3; p++) {
        const uint4* srcA = (const uint4*)g_A[p] + blockIdx.x * 1024;
        uint4* dstA = (uint4*)(smem + p * 16384);
        const uint4* srcB = (const uint4*)g_B[p] + blockIdx.y * 1024;
        uint4* dstB = (uint4*)(smem + 49152 + p * 16384);
#pragma unroll
        for (int it = 0; it < 4; it++) {
            dstA[tid + it * 256] = srcA[tid + it * 256];
            dstB[tid + it * 256] = srcB[tid + it * 256];
        }
    }
    __syncthreads();

    int warpm = wid & 3, warpn = wid >> 2;
    float acc[2][8][4] = {};

    const int GA[6] = {0, 0, 1, 1, 0, 2};
    const int GB[6] = {2, 1, 1, 0, 0, 0};

#pragma unroll
    for (int k = 0; k < 64; k += 16) {
        uint32_t a[2][4];
        uint32_t b[8][2];
#pragma unroll
        for (int s = 0; s < 6; s++) {
            if (s == 0 || GA[s] != GA[s - 1]) {
                uint32_t aBase = sb + GA[s] * 16384;
#pragma unroll
                for (int mt = 0; mt < 2; mt++) {
                    int arow = warpm * 32 + mt * 16 + (lane & 15);
                    int acol = k + ((lane >> 4) << 3);
                    uint32_t addr = swaddr(aBase, arow, acol * 2);
                    asm volatile(
                        "ldmatrix.sync.aligned.m8n8.x4.shared.b16 {%0,%1,%2,%3}, [%4];"
                        : "=r"(a[mt][0]), "=r"(a[mt][1]), "=r"(a[mt][2]),
                          "=r"(a[mt][3])
                        : "r"(addr));
                }
            }
            if (s == 0 || GB[s] != GB[s - 1]) {
                uint32_t bBase = sb + 49152 + GB[s] * 16384;
#pragma unroll
                for (int np = 0; np < 4; np++) {
                    int brow = warpn * 64 + np * 16 + ((lane >> 4) << 3) + (lane & 7);
                    int bcol = k + (((lane >> 3) & 1) << 3);
                    uint32_t addr = swaddr(bBase, brow, bcol * 2);
                    uint32_t r0, r1, r2, r3;
                    asm volatile(
                        "ldmatrix.sync.aligned.m8n8.x4.shared.b16 {%0,%1,%2,%3}, [%4];"
                        : "=r"(r0), "=r"(r1), "=r"(r2), "=r"(r3) : "r"(addr));
                    b[np * 2][0] = r0;     b[np * 2][1] = r1;
                    b[np * 2 + 1][0] = r2; b[np * 2 + 1][1] = r3;
                }
            }
#pragma unroll
            for (int mt = 0; mt < 2; mt++)
#pragma unroll
                for (int nt = 0; nt < 8; nt++) {
                    asm volatile(
                        "mma.sync.aligned.m16n8k16.row.col.f32.bf16.bf16.f32 "
                        "{%0,%1,%2,%3}, {%4,%5,%6,%7}, {%8,%9}, {%0,%1,%2,%3};"
                        : "+f"(acc[mt][nt][0]), "+f"(acc[mt][nt][1]),
                          "+f"(acc[mt][nt][2]), "+f"(acc[mt][nt][3])
                        : "r"(a[mt][0]), "r"(a[mt][1]), "r"(a[mt][2]),
                          "r"(a[mt][3]), "r"(b[nt][0]), "r"(b[nt][1]));
                }
        }
    }

    int rbase = j0 + warpm * 32 + (lane >> 2);
    int cbase = n0 + warpn * 64 + (lane & 3) * 2;
#pragma unroll
    for (int mt = 0; mt < 2; mt++)
#pragma unroll
        for (int nt = 0; nt < 8; nt++) {
            int r = rbase + mt * 16;
            int c = cbase + nt * 8;
            *(float2*)&g_H[(size_t)r * NA + c] =
                make_float2(acc[mt][nt][0], acc[mt][nt][1]);
            *(float2*)&g_H[(size_t)(r + 8) * NA + c] =
                make_float2(acc[mt][nt][2], acc[mt][nt][3]);
        }
}

// ---------------------------------------------------------------------------
// OMP, incremental-residual. This round:
//  - h[bestn] extracted from the owner lane's registers (15-SEL mux + shuffle)
//    and hbar[bestn] reconstructed as hsel + sum y_j cb_j  -> no uniform LDG
//    of g_H on the critical path.
//  - only c_1..c_3 stored in smem (24.6 KB/block); c_4 used vector-wise in
//    regs at k=4, and its k=5 broadcast value computed from one early G LDG.
//  - __launch_bounds__(128, 7): 28 warps/SM.
// ---------------------------------------------------------------------------
__global__ __launch_bounds__(128, 7) void k_omp(float* __restrict__ out) {
    __shared__ float sC[4][3 * NA];  // c_1..c_3 per warp: 24 KB
    __shared__ float bsum[4];
    int warp = threadIdx.x >> 5;
    int lane = threadIdx.x & 31;
    int j = blockIdx.x * 4 + warp;
    float* cw = sC[warp];
    float4* cw4 = (float4*)cw;

    float4 h4[4];
    const float4* hrow4 = (const float4*)(g_H + (size_t)j * NA);
    float vmax = 0.0f;
#pragma unroll
    for (int q = 0; q < 4; q++) {
        h4[q] = hrow4[lane + 32 * q];
        vmax = fmaxf(vmax, fmaxf(fmaxf(fabsf(h4[q].x), fabsf(h4[q].y)),
                                 fmaxf(fabsf(h4[q].z), fabsf(h4[q].w))));
    }

    float L[SP][SP];
    float rinv[SP];
    float y[SP];
    float x[SP];
    int I[SP];
    unsigned mask16 = 0;

#pragma unroll
    for (int k = 1; k <= SP; k++) {
        // ---- warp max ----
#pragma unroll
        for (int off = 16; off; off >>= 1)
            vmax = fmaxf(vmax, __shfl_xor_sync(0xFFFFFFFFu, vmax, off));

        // ---- equality bitmask (bit = 4q+e; n = 4*lane + 128q + e) ----
        unsigned eq = 0;
#pragma unroll
        for (int q = 0; q < 4; q++) {
            if (fabsf(h4[q].x) == vmax) eq |= 1u << (4 * q + 0);
            if (fabsf(h4[q].y) == vmax) eq |= 1u << (4 * q + 1);
            if (fabsf(h4[q].z) == vmax) eq |= 1u << (4 * q + 2);
            if (fabsf(h4[q].w) == vmax) eq |= 1u << (4 * q + 3);
        }
        int b = __ffs(eq | 0x10000u) - 1;  // lane's first-eq bit (junk-safe)
        int ncand = eq ? ((lane << 2) | ((b >> 2) << 7) | (b & 3)) : 0x7FFFFFFF;
        int bestn = __reduce_min_sync(0xFFFFFFFFu, ncand);
        I[k - 1] = bestn;

        // early G LDG for the k=5 c4-broadcast reconstruction
        float g45 = 0.0f;
        if (k == SP) g45 = __ldg(g_G + (size_t)I[3] * NA + bestn);

        // ---- owner-lane extraction of h[bestn] (signed, exact) ----
        float4 m0x = (b & 4) ? h4[1] : h4[0];
        float4 m1x = (b & 4) ? h4[3] : h4[2];
        float4 mm = (b & 8) ? m1x : m0x;
        float p0 = (b & 1) ? mm.y : mm.x;
        float p1 = (b & 1) ? mm.w : mm.z;
        float hown = (b & 2) ? p1 : p0;
        float hsel = __shfl_sync(0xFFFFFFFFu, hown, (bestn >> 2) & 31);

        // ---- broadcasts of c_j[bestn] ----
        float cb[4];
#pragma unroll
        for (int jj = 0; jj < 3; jj++)
            if (jj < k - 1) cb[jj] = cw[jj * NA + bestn];
        if (k == SP)
            cb[3] = (g45 - L[3][0] * cb[0] - L[3][1] * cb[1] -
                     L[3][2] * cb[2]) * rinv[3];

        // ---- hbar[bestn] reconstruction ----
        float hbk = hsel;
#pragma unroll
        for (int jj = 0; jj < 4; jj++)
            if (jj < k - 1) hbk += y[jj] * cb[jj];

        // ---- L row k (division-free); gv_i = sum_{jj<=i} L_ij cb_jj ----
        if (k == 1) {
            L[0][0] = 1.0f;
            rinv[0] = 1.0f;
        } else {
            float w[SP - 1];
            float ss = 0.0f;
#pragma unroll
            for (int i = 0; i < SP - 1; i++) {
                if (i < k - 1) {
                    float gvi = 0.0f;
#pragma unroll
                    for (int jj = 0; jj < SP - 1; jj++)
                        if (jj <= i) gvi += L[i][jj] * cb[jj];
                    float s = gvi;
#pragma unroll
                    for (int j2 = 0; j2 < SP - 1; j2++)
                        if (j2 < i) s -= L[i][j2] * w[j2];
                    w[i] = s * rinv[i];
                    ss += w[i] * w[i];
                }
            }
#pragma unroll
            for (int j2 = 0; j2 < SP - 1; j2++)
                if (j2 < k - 1) L[k - 1][j2] = w[j2];
            float v = fmaxf(1.0f - ss, 0.0f);
            float rs = rsqrtf(v);
            L[k - 1][k - 1] = v * rs;
            rinv[k - 1] = rs;
        }

        // ---- y_k ----
        {
            float s = hbk;
#pragma unroll
            for (int j2 = 0; j2 < SP - 1; j2++)
                if (j2 < k - 1) s -= L[k - 1][j2] * y[j2];
            y[k - 1] = s * rinv[k - 1];
        }

        // ---- mask the new atom ----
        if (((bestn >> 2) & 31) == lane)
            mask16 |= 1u << (((bestn >> 7) << 2) | (bestn & 3));

        // ---- c_k + h update, fused next-max (skipped for last iteration) ----
        if (k < SP) {
            const float4* grow4 = (const float4*)(g_G + (size_t)bestn * NA);
            float yk = y[k - 1];
            float rk = rinv[k - 1];
            vmax = 0.0f;
#pragma unroll
            for (int q = 0; q < 4; q++) {
                float4 c4 = grow4[lane + 32 * q];
#pragma unroll
                for (int jj = 0; jj < 3; jj++) {
                    if (jj < k - 1) {
                        float lkj = L[k - 1][jj];
                        float4 cj = cw4[jj * 128 + lane + 32 * q];
                        c4.x -= lkj * cj.x; c4.y -= lkj * cj.y;
                        c4.z -= lkj * cj.z; c4.w -= lkj * cj.w;
                    }
                }
                c4.x *= rk; c4.y *= rk; c4.z *= rk; c4.w *= rk;
                if (k - 1 < 3) cw4[(k - 1) * 128 + lane + 32 * q] = c4;
                float4 hh = h4[q];
                hh.x -= yk * c4.x; hh.y -= yk * c4.y;
                hh.z -= yk * c4.z; hh.w -= yk * c4.w;
                if ((mask16 >> (q * 4 + 0)) & 1u) hh.x = 0.0f;
                if ((mask16 >> (q * 4 + 1)) & 1u) hh.y = 0.0f;
                if ((mask16 >> (q * 4 + 2)) & 1u) hh.z = 0.0f;
                if ((mask16 >> (q * 4 + 3)) & 1u) hh.w = 0.0f;
                h4[q] = hh;
                vmax = fmaxf(vmax, fmaxf(fmaxf(fabsf(hh.x), fabsf(hh.y)),
                                         fmaxf(fabsf(hh.z), fabsf(hh.w))));
            }
            __syncwarp();
        }
    }

    // ---- x = L^-T y (back substitution, division-free) ----
#pragma unroll
    for (int i = SP - 1; i >= 0; i--) {
        float s = y[i];
#pragma unroll
        for (int j2 = i + 1; j2 < SP; j2++) s -= L[j2][i] * x[j2];
        x[i] = s * rinv[i];
    }

    // ---- reconstruction + outputs ----
    float ze0 = g_Zt[j * MD + lane];
    float ze1 = g_Zt[j * MD + 32 + lane];
    float r0 = 0.f, r1 = 0.f;
#pragma unroll
    for (int i = 0; i < SP; i++) {
        const float* dcol = g_Dt + I[i] * MD;
        r0 += x[i] * dcol[lane];
        r1 += x[i] * dcol[32 + lane];
    }

    // z_out scattered back to NCHW: c=f&63, w=(f>>6)&31, h=(f>>11)&31, b=f>>16
#pragma unroll
    for (int p = 0; p < 2; p++) {
        int m = lane + 32 * p;
        float rm = p ? r1 : r0;
        float ze = p ? ze1 : ze0;
        float zo = ze + (rm - ze);
        int f = (m << 15) | j;
        int c = f & 63, ww = (f >> 6) & 31, hh = (f >> 11) & 31, bb = f >> 16;
        __stcs(&out[((bb * 64 + c) * 32 + hh) * 32 + ww], zo);
    }

    float d0 = r0 - ze0, d1 = r1 - ze1;
    float s = d0 * d0 + d1 * d1;
#pragma unroll
    for (int off = 16; off; off >>= 1) s += __shfl_xor_sync(0xFFFFFFFFu, s, off);
    if (lane == 0) bsum[warp] = s;
    __syncthreads();
    if (threadIdx.x == 0) {
        float t = bsum[0] + bsum[1] + bsum[2] + bsum[3];
        atomicAdd(out + LOSS_OFF, t * (1.25f / (float)ZELEMS));
    }

    if (lane == 0) {
        float* co = out + COEF_OFF;
        __stcs(&co[(size_t)I[0] * NB + j], x[0]);
        __stcs(&co[(size_t)I[1] * NB + j], x[1]);
        __stcs(&co[(size_t)I[2] * NB + j], x[2]);
        __stcs(&co[(size_t)I[3] * NB + j], x[3]);
        __stcs(&co[(size_t)I[4] * NB + j], x[4]);
    }
}

// ---------------------------------------------------------------------------
extern "C" void kernel_launch(void* const* d_in, const int* in_sizes, int n_in,
                              void* d_out, int out_size) {
    const float* ze = (const float*)d_in[0];  // (32, 64, 32, 32)
    const float* D = (const float*)d_in[1];   // (64, 512)
    float* out = (float*)d_out;

    cudaFuncSetAttribute(k_gemm_mma,
                         cudaFuncAttributeMaxDynamicSharedMemorySize, 98304);

    int ztail = out_size - LOSS_OFF;  // loss + coefficients
    k_prep<<<4096, 256>>>(out, ztail, D);
    k_ssplit<<<1024, 256>>>(ze);
    k_gemm_mma<<<dim3(NB / 128, NA / 128), 256, 98304>>>();
    k_omp<<<NB / 4, 128>>>(out);
}

// round 11
// speedup vs baseline: 1.6095x; 1.0327x over previous
#include <cuda_runtime.h>
#include <cuda_bf16.h>
#include <cstdint>

// Problem constants
#define NB 32768   // number of signals (B)
#define NA 512     // number of atoms (N)
#define MD 64      // embedding dim (M)
#define SP 5       // sparsity
#define ZELEMS 2097152        // 32*64*32*32
#define LOSS_OFF ZELEMS       // loss scalar offset in d_out
#define COEF_OFF (ZELEMS + 1) // coefficients offset in d_out

// Scratch (static __device__ — no allocation allowed)
__device__ float g_Zt[NB * MD];   // Z transposed: [j][m], 8 MB
__device__ float g_H[NB * NA];    // h_bar: [j][n], 64 MB (keep L2-warm)
__device__ float g_G[NA * NA];    // Gram D^T D, 1 MB
__device__ float g_Dt[NA * MD];   // D transposed: [n][m], 128 KB
// bf16 3-way-split operands, pre-swizzled rows of 128 B
__device__ __align__(16) __nv_bfloat16 g_A[3][NB * MD];
__device__ __align__(16) __nv_bfloat16 g_B[3][NA * MD];

__host__ __device__ __forceinline__ uint32_t sw128(uint32_t o) {
    return o ^ ((o >> 3) & 0x70);
}
__device__ __forceinline__ uint32_t smem_u32(const void* p) {
    uint32_t a;
    asm("{ .reg .u64 t; cvta.to.shared.u64 t, %1; cvt.u32.u64 %0, t; }"
        : "=r"(a) : "l"(p));
    return a;
}
__device__ __forceinline__ uint32_t swaddr(uint32_t base, int row, int colbyte) {
    uint32_t o = (uint32_t)(row * 128 + colbyte);
    return base + (o ^ ((uint32_t)(row & 7) << 4));
}

// ---------------------------------------------------------------------------
// k_prep: zero loss+coef (streaming stores), Dt transpose + B split,
// and (blocks < 256) the Gram matrix tiles.
// ---------------------------------------------------------------------------
__global__ void k_prep(float* __restrict__ out, int nfloats,
                       const float* __restrict__ D) {
    __shared__ float Da[32 * 65];
    __shared__ float Db[32 * 65];
    int tid = blockIdx.x * blockDim.x + threadIdx.x;

    float4* p = (float4*)(out + LOSS_OFF);
    int n4 = nfloats >> 2;
    float4 z4 = make_float4(0.f, 0.f, 0.f, 0.f);
    for (int i = tid; i < n4; i += gridDim.x * blockDim.x) __stcs(p + i, z4);
    if (blockIdx.x == 0 && threadIdx.x < (nfloats & 3))
        out[LOSS_OFF + (n4 << 2) + threadIdx.x] = 0.f;

    if (tid < MD * NA) {
        int m = tid >> 9;
        int n = tid & (NA - 1);
        float v = D[tid];
        g_Dt[n * MD + m] = v;
        __nv_bfloat16 bh = __float2bfloat16(v);
        float r1 = v - __bfloat162float(bh);
        __nv_bfloat16 bm = __float2bfloat16(r1);
        float r2 = r1 - __bfloat162float(bm);
        __nv_bfloat16 bl = __float2bfloat16(r2);
        uint32_t so = sw128((uint32_t)(n * 128 + m * 2));
        *(__nv_bfloat16*)((char*)g_B[0] + so) = bh;
        *(__nv_bfloat16*)((char*)g_B[1] + so) = bm;
        *(__nv_bfloat16*)((char*)g_B[2] + so) = bl;
    }

    // Gram tiles on blocks [0, 256)
    if (blockIdx.x < 256) {
        int a0 = (blockIdx.x >> 4) * 32, b0 = (blockIdx.x & 15) * 32;
        int t = threadIdx.x;  // 256
#pragma unroll
        for (int it = 0; it < 8; it++) {
            int e = t + it * 256;
            int aa = e & 31, m = e >> 5;
            Da[aa * 65 + m] = D[m * NA + a0 + aa];
            Db[aa * 65 + m] = D[m * NA + b0 + aa];
        }
        __syncthreads();
        int tb = t & 15, ta = t >> 4;
        float acc[2][2] = {};
#pragma unroll
        for (int m = 0; m < MD; m++) {
            float a0v = Da[(2 * ta) * 65 + m];
            float a1v = Da[(2 * ta + 1) * 65 + m];
            float b0v = Db[(2 * tb) * 65 + m];
            float b1v = Db[(2 * tb + 1) * 65 + m];
            acc[0][0] += a0v * b0v; acc[0][1] += a0v * b1v;
            acc[1][0] += a1v * b0v; acc[1][1] += a1v * b1v;
        }
#pragma unroll
        for (int i = 0; i < 2; i++)
#pragma unroll
            for (int l = 0; l < 2; l++)
                g_G[(a0 + 2 * ta + i) * NA + (b0 + 2 * tb + l)] = acc[i][l];
    }
}

// ---------------------------------------------------------------------------
// Fused scatter + bf16 split.
// Inverse map: for f = m*32768+j,  g = (m>>1)<<16 | (j&63)<<10 | (m&1)<<9
//                                      | ((j>>11)&15)<<5 | ((j>>6)&31)
// ---------------------------------------------------------------------------
__global__ void k_ssplit(const float* __restrict__ ze) {
    int t = blockIdx.x * blockDim.x + threadIdx.x;  // 262144
    int lane = t & 31;
    int grp = (t >> 5) & 7;         // m-group of 8
    int jlow6 = (t >> 8) & 63;      // c
    int jhi4 = t >> 14;             // j>>11
    int j = (jhi4 << 11) | (lane << 6) | jlow6;

    int base_g = ((grp * 4) << 16) | (jlow6 << 10) | (jhi4 << 5) | lane;
    float v[8];
#pragma unroll
    for (int e = 0; e < 8; e++)
        v[e] = __ldcs(ze + base_g + ((e >> 1) << 16) + ((e & 1) << 9));

    float4* zt4 = (float4*)(g_Zt + j * MD + grp * 8);
    zt4[0] = make_float4(v[0], v[1], v[2], v[3]);
    zt4[1] = make_float4(v[4], v[5], v[6], v[7]);

    unsigned short hs[8], ms[8], ls[8];
#pragma unroll
    for (int i = 0; i < 8; i++) {
        __nv_bfloat16 bh = __float2bfloat16(v[i]);
        float r1 = v[i] - __bfloat162float(bh);
        __nv_bfloat16 bm = __float2bfloat16(r1);
        float r2 = r1 - __bfloat162float(bm);
        __nv_bfloat16 bl = __float2bfloat16(r2);
        hs[i] = __bfloat16_as_ushort(bh);
        ms[i] = __bfloat16_as_ushort(bm);
        ls[i] = __bfloat16_as_ushort(bl);
    }
    int tile = j >> 7, r = j & 127;
    uint32_t so = sw128((uint32_t)(r * 128 + grp * 16));
    size_t off = (size_t)tile * 16384 + so;
    *(uint4*)((char*)g_A[0] + off) =
        make_uint4(hs[0] | (hs[1] << 16), hs[2] | (hs[3] << 16),
                   hs[4] | (hs[5] << 16), hs[6] | (hs[7] << 16));
    *(uint4*)((char*)g_A[1] + off) =
        make_uint4(ms[0] | (ms[1] << 16), ms[2] | (ms[3] << 16),
                   ms[4] | (ms[5] << 16), ms[6] | (ms[7] << 16));
    *(uint4*)((char*)g_A[2] + off) =
        make_uint4(ls[0] | (ls[1] << 16), ls[2] | (ls[3] << 16),
                   ls[4] | (ls[5] << 16), ls[6] | (ls[7] << 16));
}

// ---------------------------------------------------------------------------
// HMMA GEMM, 3-way bf16 split, gray-code product order.
// ---------------------------------------------------------------------------
__global__ __launch_bounds__(256, 2) void k_gemm_mma() {
    extern __shared__ char smem[];
    uint32_t sb = smem_u32(smem);
    int tid = threadIdx.x;
    int wid = tid >> 5, lane = tid & 31;
    int j0 = blockIdx.x * 128;
    int n0 = blockIdx.y * 128;

#pragma unroll
    for (int p = 0; p < 3; p++) {
        const uint4* srcA = (const uint4*)g_A[p] + blockIdx.x * 1024;
        uint4* dstA = (uint4*)(smem + p * 16384);
        const uint4* srcB = (const uint4*)g_B[p] + blockIdx.y * 1024;
        uint4* dstB = (uint4*)(smem + 49152 + p * 16384);
#pragma unroll
        for (int it = 0; it < 4; it++) {
            dstA[tid + it * 256] = srcA[tid + it * 256];
            dstB[tid + it * 256] = srcB[tid + it * 256];
        }
    }
    __syncthreads();

    int warpm = wid & 3, warpn = wid >> 2;
    float acc[2][8][4] = {};

    const int GA[6] = {0, 0, 1, 1, 0, 2};
    const int GB[6] = {2, 1, 1, 0, 0, 0};

#pragma unroll
    for (int k = 0; k < 64; k += 16) {
        uint32_t a[2][4];
        uint32_t b[8][2];
#pragma unroll
        for (int s = 0; s < 6; s++) {
            if (s == 0 || GA[s] != GA[s - 1]) {
                uint32_t aBase = sb + GA[s] * 16384;
#pragma unroll
                for (int mt = 0; mt < 2; mt++) {
                    int arow = warpm * 32 + mt * 16 + (lane & 15);
                    int acol = k + ((lane >> 4) << 3);
                    uint32_t addr = swaddr(aBase, arow, acol * 2);
                    asm volatile(
                        "ldmatrix.sync.aligned.m8n8.x4.shared.b16 {%0,%1,%2,%3}, [%4];"
                        : "=r"(a[mt][0]), "=r"(a[mt][1]), "=r"(a[mt][2]),
                          "=r"(a[mt][3])
                        : "r"(addr));
                }
            }
            if (s == 0 || GB[s] != GB[s - 1]) {
                uint32_t bBase = sb + 49152 + GB[s] * 16384;
#pragma unroll
                for (int np = 0; np < 4; np++) {
                    int brow = warpn * 64 + np * 16 + ((lane >> 4) << 3) + (lane & 7);
                    int bcol = k + (((lane >> 3) & 1) << 3);
                    uint32_t addr = swaddr(bBase, brow, bcol * 2);
                    uint32_t r0, r1, r2, r3;
                    asm volatile(
                        "ldmatrix.sync.aligned.m8n8.x4.shared.b16 {%0,%1,%2,%3}, [%4];"
                        : "=r"(r0), "=r"(r1), "=r"(r2), "=r"(r3) : "r"(addr));
                    b[np * 2][0] = r0;     b[np * 2][1] = r1;
                    b[np * 2 + 1][0] = r2; b[np * 2 + 1][1] = r3;
                }
            }
#pragma unroll
            for (int mt = 0; mt < 2; mt++)
#pragma unroll
                for (int nt = 0; nt < 8; nt++) {
                    asm volatile(
                        "mma.sync.aligned.m16n8k16.row.col.f32.bf16.bf16.f32 "
                        "{%0,%1,%2,%3}, {%4,%5,%6,%7}, {%8,%9}, {%0,%1,%2,%3};"
                        : "+f"(acc[mt][nt][0]), "+f"(acc[mt][nt][1]),
                          "+f"(acc[mt][nt][2]), "+f"(acc[mt][nt][3])
                        : "r"(a[mt][0]), "r"(a[mt][1]), "r"(a[mt][2]),
                          "r"(a[mt][3]), "r"(b[nt][0]), "r"(b[nt][1]));
                }
        }
    }

    int rbase = j0 + warpm * 32 + (lane >> 2);
    int cbase = n0 + warpn * 64 + (lane & 3) * 2;
#pragma unroll
    for (int mt = 0; mt < 2; mt++)
#pragma unroll
        for (int nt = 0; nt < 8; nt++) {
            int r = rbase + mt * 16;
            int c = cbase + nt * 8;
            *(float2*)&g_H[(size_t)r * NA + c] =
                make_float2(acc[mt][nt][0], acc[mt][nt][1]);
            *(float2*)&g_H[(size_t)(r + 8) * NA + c] =
                make_float2(acc[mt][nt][2], acc[mt][nt][3]);
        }
}

// ---------------------------------------------------------------------------
// OMP, incremental-residual. This round:
//  - warp value-max via one __reduce_max_sync on uint bits of |h| (monotone
//    for non-negative floats) — replaces the 5-step shuffle tree.
//  - 8 warps/block (48 KB smem, 4 blocks/SM -> 32 warps/SM).
// ---------------------------------------------------------------------------
__global__ __launch_bounds__(256, 4) void k_omp(float* __restrict__ out) {
    __shared__ float sC[8][3 * NA];  // c_1..c_3 per warp: 48 KB
    __shared__ float bsum[8];
    int warp = threadIdx.x >> 5;
    int lane = threadIdx.x & 31;
    int j = blockIdx.x * 8 + warp;
    float* cw = sC[warp];
    float4* cw4 = (float4*)cw;

    float4 h4[4];
    const float4* hrow4 = (const float4*)(g_H + (size_t)j * NA);
    float lmax = 0.0f;
#pragma unroll
    for (int q = 0; q < 4; q++) {
        h4[q] = hrow4[lane + 32 * q];
        lmax = fmaxf(lmax, fmaxf(fmaxf(fabsf(h4[q].x), fabsf(h4[q].y)),
                                 fmaxf(fabsf(h4[q].z), fabsf(h4[q].w))));
    }

    float L[SP][SP];
    float rinv[SP];
    float y[SP];
    float x[SP];
    int I[SP];
    unsigned mask16 = 0;

#pragma unroll
    for (int k = 1; k <= SP; k++) {
        // ---- warp max via REDUX (uint-monotone for |h| >= 0) ----
        float vmax = __uint_as_float(
            __reduce_max_sync(0xFFFFFFFFu, __float_as_uint(lmax)));

        // ---- equality bitmask (bit = 4q+e; n = 4*lane + 128q + e) ----
        unsigned eq = 0;
#pragma unroll
        for (int q = 0; q < 4; q++) {
            if (fabsf(h4[q].x) == vmax) eq |= 1u << (4 * q + 0);
            if (fabsf(h4[q].y) == vmax) eq |= 1u << (4 * q + 1);
            if (fabsf(h4[q].z) == vmax) eq |= 1u << (4 * q + 2);
            if (fabsf(h4[q].w) == vmax) eq |= 1u << (4 * q + 3);
        }
        int b = __ffs(eq | 0x10000u) - 1;  // lane's first-eq bit (junk-safe)
        int ncand = eq ? ((lane << 2) | ((b >> 2) << 7) | (b & 3)) : 0x7FFFFFFF;
        int bestn = __reduce_min_sync(0xFFFFFFFFu, ncand);
        I[k - 1] = bestn;

        // early G LDG for the k=5 c4-broadcast reconstruction
        float g45 = 0.0f;
        if (k == SP) g45 = __ldg(g_G + (size_t)I[3] * NA + bestn);

        // ---- owner-lane extraction of h[bestn] (signed, exact) ----
        float4 m0x = (b & 4) ? h4[1] : h4[0];
        float4 m1x = (b & 4) ? h4[3] : h4[2];
        float4 mm = (b & 8) ? m1x : m0x;
        float p0 = (b & 1) ? mm.y : mm.x;
        float p1 = (b & 1) ? mm.w : mm.z;
        float hown = (b & 2) ? p1 : p0;
        float hsel = __shfl_sync(0xFFFFFFFFu, hown, (bestn >> 2) & 31);

        // ---- broadcasts of c_j[bestn] ----
        float cb[4];
#pragma unroll
        for (int jj = 0; jj < 3; jj++)
            if (jj < k - 1) cb[jj] = cw[jj * NA + bestn];
        if (k == SP)
            cb[3] = (g45 - L[3][0] * cb[0] - L[3][1] * cb[1] -
                     L[3][2] * cb[2]) * rinv[3];

        // ---- hbar[bestn] reconstruction ----
        float hbk = hsel;
#pragma unroll
        for (int jj = 0; jj < 4; jj++)
            if (jj < k - 1) hbk += y[jj] * cb[jj];

        // ---- L row k (division-free); gv_i = sum_{jj<=i} L_ij cb_jj ----
        if (k == 1) {
            L[0][0] = 1.0f;
            rinv[0] = 1.0f;
        } else {
            float w[SP - 1];
            float ss = 0.0f;
#pragma unroll
            for (int i = 0; i < SP - 1; i++) {
                if (i < k - 1) {
                    float gvi = 0.0f;
#pragma unroll
                    for (int jj = 0; jj < SP - 1; jj++)
                        if (jj <= i) gvi += L[i][jj] * cb[jj];
                    float s = gvi;
#pragma unroll
                    for (int j2 = 0; j2 < SP - 1; j2++)
                        if (j2 < i) s -= L[i][j2] * w[j2];
                    w[i] = s * rinv[i];
                    ss += w[i] * w[i];
                }
            }
#pragma unroll
            for (int j2 = 0; j2 < SP - 1; j2++)
                if (j2 < k - 1) L[k - 1][j2] = w[j2];
            float v = fmaxf(1.0f - ss, 0.0f);
            float rs = rsqrtf(v);
            L[k - 1][k - 1] = v * rs;
            rinv[k - 1] = rs;
        }

        // ---- y_k ----
        {
            float s = hbk;
#pragma unroll
            for (int j2 = 0; j2 < SP - 1; j2++)
                if (j2 < k - 1) s -= L[k - 1][j2] * y[j2];
            y[k - 1] = s * rinv[k - 1];
        }

        // ---- mask the new atom ----
        if (((bestn >> 2) & 31) == lane)
            mask16 |= 1u << (((bestn >> 7) << 2) | (bestn & 3));

        // ---- c_k + h update, fused next-max (skipped for last iteration) ----
        if (k < SP) {
            const float4* grow4 = (const float4*)(g_G + (size_t)bestn * NA);
            float yk = y[k - 1];
            float rk = rinv[k - 1];
            lmax = 0.0f;
#pragma unroll
            for (int q = 0; q < 4; q++) {
                float4 c4 = grow4[lane + 32 * q];
#pragma unroll
                for (int jj = 0; jj < 3; jj++) {
                    if (jj < k - 1) {
                        float lkj = L[k - 1][jj];
                        float4 cj = cw4[jj * 128 + lane + 32 * q];
                        c4.x -= lkj * cj.x; c4.y -= lkj * cj.y;
                        c4.z -= lkj * cj.z; c4.w -= lkj * cj.w;
                    }
                }
                c4.x *= rk; c4.y *= rk; c4.z *= rk; c4.w *= rk;
                if (k - 1 < 3) cw4[(k - 1) * 128 + lane + 32 * q] = c4;
                float4 hh = h4[q];
                hh.x -= yk * c4.x; hh.y -= yk * c4.y;
                hh.z -= yk * c4.z; hh.w -= yk * c4.w;
                if ((mask16 >> (q * 4 + 0)) & 1u) hh.x = 0.0f;
                if ((mask16 >> (q * 4 + 1)) & 1u) hh.y = 0.0f;
                if ((mask16 >> (q * 4 + 2)) & 1u) hh.z = 0.0f;
                if ((mask16 >> (q * 4 + 3)) & 1u) hh.w = 0.0f;
                h4[q] = hh;
                lmax = fmaxf(lmax, fmaxf(fmaxf(fabsf(hh.x), fabsf(hh.y)),
                                         fmaxf(fabsf(hh.z), fabsf(hh.w))));
            }
            __syncwarp();
        }
    }

    // ---- x = L^-T y (back substitution, division-free) ----
#pragma unroll
    for (int i = SP - 1; i >= 0; i--) {
        float s = y[i];
#pragma unroll
        for (int j2 = i + 1; j2 < SP; j2++) s -= L[j2][i] * x[j2];
        x[i] = s * rinv[i];
    }

    // ---- reconstruction + outputs ----
    float ze0 = g_Zt[j * MD + lane];
    float ze1 = g_Zt[j * MD + 32 + lane];
    float r0 = 0.f, r1 = 0.f;
#pragma unroll
    for (int i = 0; i < SP; i++) {
        const float* dcol = g_Dt + I[i] * MD;
        r0 += x[i] * dcol[lane];
        r1 += x[i] * dcol[32 + lane];
    }

    // z_out scattered back to NCHW: c=f&63, w=(f>>6)&31, h=(f>>11)&31, b=f>>16
#pragma unroll
    for (int p = 0; p < 2; p++) {
        int m = lane + 32 * p;
        float rm = p ? r1 : r0;
        float ze = p ? ze1 : ze0;
        float zo = ze + (rm - ze);
        int f = (m << 15) | j;
        int c = f & 63, ww = (f >> 6) & 31, hh = (f >> 11) & 31, bb = f >> 16;
        __stcs(&out[((bb * 64 + c) * 32 + hh) * 32 + ww], zo);
    }

    float d0 = r0 - ze0, d1 = r1 - ze1;
    float s = d0 * d0 + d1 * d1;
#pragma unroll
    for (int off = 16; off; off >>= 1) s += __shfl_xor_sync(0xFFFFFFFFu, s, off);
    if (lane == 0) bsum[warp] = s;
    __syncthreads();
    if (threadIdx.x == 0) {
        float t = 0.0f;
#pragma unroll
        for (int wq = 0; wq < 8; wq++) t += bsum[wq];
        atomicAdd(out + LOSS_OFF, t * (1.25f / (float)ZELEMS));
    }

    if (lane == 0) {
        float* co = out + COEF_OFF;
        __stcs(&co[(size_t)I[0] * NB + j], x[0]);
        __stcs(&co[(size_t)I[1] * NB + j], x[1]);
        __stcs(&co[(size_t)I[2] * NB + j], x[2]);
        __stcs(&co[(size_t)I[3] * NB + j], x[3]);
        __stcs(&co[(size_t)I[4] * NB + j], x[4]);
    }
}

// ---------------------------------------------------------------------------
extern "C" void kernel_launch(void* const* d_in, const int* in_sizes, int n_in,
                              void* d_out, int out_size) {
    const float* ze = (const float*)d_in[0];  // (32, 64, 32, 32)
    const float* D = (const float*)d_in[1];   // (64, 512)
    float* out = (float*)d_out;

    cudaFuncSetAttribute(k_gemm_mma,
                         cudaFuncAttributeMaxDynamicSharedMemorySize, 98304);

    int ztail = out_size - LOSS_OFF;  // loss + coefficients
    k_prep<<<4096, 256>>>(out, ztail, D);
    k_ssplit<<<1024, 256>>>(ze);
    k_gemm_mma<<<dim3(NB / 128, NA / 128), 256, 98304>>>();
    k_omp<<<NB / 8, 256>>>(out);
}